// round 1
// baseline (speedup 1.0000x reference)
#include <cuda_runtime.h>
#include <math.h>

#define B_    2
#define T_    2048
#define DIM_  2048
#define NH_   16
#define NKV_  4
#define HD_   128
#define KD_   512
#define GQ_   (NH_ / NKV_)
#define EPS_  1.1920928955078125e-07f

// ---------------- scratch (static device arrays; no allocation allowed) ----
__device__ float g_q[(size_t)B_ * T_ * DIM_];   // (B,T,NH,HD)
__device__ float g_k[(size_t)B_ * T_ * KD_];    // (B,T,NKV,HD)
__device__ float g_v[(size_t)B_ * T_ * KD_];    // (B,T,NKV,HD)
__device__ float g_y[(size_t)B_ * T_ * DIM_];   // attention output (B,T,NH,HD)
__device__ float g_cos[T_ * (HD_ / 2)];
__device__ float g_sin[T_ * (HD_ / 2)];

// ---------------- RoPE tables (fp64 for accuracy, tiny kernel) -------------
__global__ void rope_table_kernel() {
    int idx = blockIdx.x * blockDim.x + threadIdx.x;
    if (idx >= T_ * (HD_ / 2)) return;
    int t = idx >> 6;          // HD/2 = 64
    int i = idx & 63;
    double base = 10000.0;
    if (T_ > 1024)
        base = 10000.0 * pow((double)T_ / 1024.0, (double)HD_ / (double)(HD_ - 2));
    double f = pow(base, -((double)(2 * i)) / (double)HD_);
    double a = (double)t * f;
    g_cos[idx] = (float)cos(a);
    g_sin[idx] = (float)sin(a);
}

// ---------------- generic NT SGEMM: C[M,N] = A[M,K] * B[N,K]^T --------------
// 128x128 block tile, BK=16, 256 threads, 8x8 per-thread microtile.
__global__ void __launch_bounds__(256, 2) sgemm_nt(
    const float* __restrict__ A, const float* __restrict__ B,
    float* __restrict__ C, int M, int N, int K)
{
    __shared__ float As[16][128];
    __shared__ float Bs[16][128];

    const int bm  = blockIdx.y * 128;
    const int bn  = blockIdx.x * 128;
    const int tid = threadIdx.x;
    const int tx  = tid & 15;
    const int ty  = tid >> 4;

    float acc[8][8];
    #pragma unroll
    for (int i = 0; i < 8; ++i)
        #pragma unroll
        for (int j = 0; j < 8; ++j) acc[i][j] = 0.f;

    const float* Ab = A + (size_t)bm * K;
    const float* Bb = B + (size_t)bn * K;

    for (int k0 = 0; k0 < K; k0 += 16) {
        #pragma unroll
        for (int r = 0; r < 2; ++r) {
            int f   = tid + r * 256;
            int row = f >> 2;
            int c4  = (f & 3) << 2;
            float4 va = *(const float4*)(Ab + (size_t)row * K + k0 + c4);
            As[c4 + 0][row] = va.x; As[c4 + 1][row] = va.y;
            As[c4 + 2][row] = va.z; As[c4 + 3][row] = va.w;
            float4 vb = *(const float4*)(Bb + (size_t)row * K + k0 + c4);
            Bs[c4 + 0][row] = vb.x; Bs[c4 + 1][row] = vb.y;
            Bs[c4 + 2][row] = vb.z; Bs[c4 + 3][row] = vb.w;
        }
        __syncthreads();

        #pragma unroll
        for (int k = 0; k < 16; ++k) {
            float a[8], b[8];
            *(float4*)(&a[0]) = *(const float4*)(&As[k][ty * 4]);
            *(float4*)(&a[4]) = *(const float4*)(&As[k][64 + ty * 4]);
            *(float4*)(&b[0]) = *(const float4*)(&Bs[k][tx * 4]);
            *(float4*)(&b[4]) = *(const float4*)(&Bs[k][64 + tx * 4]);
            #pragma unroll
            for (int i = 0; i < 8; ++i)
                #pragma unroll
                for (int j = 0; j < 8; ++j)
                    acc[i][j] += a[i] * b[j];
        }
        __syncthreads();
    }

    #pragma unroll
    for (int i = 0; i < 8; ++i) {
        int m = bm + (i < 4 ? ty * 4 + i : 64 + ty * 4 + (i - 4));
        float4 v0 = make_float4(acc[i][0], acc[i][1], acc[i][2], acc[i][3]);
        float4 v1 = make_float4(acc[i][4], acc[i][5], acc[i][6], acc[i][7]);
        *(float4*)(C + (size_t)m * N + bn + tx * 4)      = v0;
        *(float4*)(C + (size_t)m * N + bn + 64 + tx * 4) = v1;
    }
}

// ---------------- RMSNorm + RoPE (+gain) : one warp per head vector --------
__global__ void norm_rope_kernel(float* __restrict__ data,
                                 const float* __restrict__ gain, int nheads)
{
    int gw   = (blockIdx.x * blockDim.x + threadIdx.x) >> 5;
    int lane = threadIdx.x & 31;
    int h = gw % nheads;
    int t = (gw / nheads) % T_;

    float4 v = *(const float4*)(data + (size_t)gw * HD_ + lane * 4);
    float ss = v.x * v.x + v.y * v.y + v.z * v.z + v.w * v.w;
    #pragma unroll
    for (int off = 16; off; off >>= 1)
        ss += __shfl_xor_sync(0xffffffffu, ss, off);
    float r = rsqrtf(ss * (1.f / HD_) + EPS_);

    float x[4] = { v.x * r, v.y * r, v.z * r, v.w * r };
    bool hi = lane >= 16;
    float g = gain ? gain[h] : 1.f;

    float out[4];
    #pragma unroll
    for (int j = 0; j < 4; ++j) {
        float p = __shfl_xor_sync(0xffffffffu, x[j], 16);
        int i   = (lane & 15) * 4 + j;
        float c = g_cos[t * 64 + i];
        float s = g_sin[t * 64 + i];
        // lo half:  x1*c + x2*s ; hi half: -x1*s + x2*c
        out[j] = (hi ? (x[j] * c - p * s) : (x[j] * c + p * s)) * g;
    }
    *(float4*)(data + (size_t)gw * HD_ + lane * 4) =
        make_float4(out[0], out[1], out[2], out[3]);
}

// ---------------- causal flash attention (fp32, 64x64 tiles) ---------------
// grid: (T/64, NH, B), 256 threads. Thread (ty,tx) in 16x16 grid owns
// S rows 4*ty+i (i<4), S cols tx+16*jj (jj<4), O cols tx+16*dj (dj<8).
#define QS_STRIDE 132
#define PS_STRIDE 65

__global__ void __launch_bounds__(256) flash_kernel(
    const float* __restrict__ q, const float* __restrict__ k,
    const float* __restrict__ v, float* __restrict__ y)
{
    extern __shared__ float sm[];
    float* Qs = sm;                        // [64][132]
    float* Ks = Qs + 64 * QS_STRIDE;       // [64][132]
    float* Vs = Ks + 64 * QS_STRIDE;       // [64][132]
    float* Ps = Vs + 64 * QS_STRIDE;       // [64][65]

    const int it  = blockIdx.x;
    const int h   = blockIdx.y;
    const int b   = blockIdx.z;
    const int kv  = h / GQ_;
    const int tid = threadIdx.x;
    const int tx  = tid & 15;
    const int ty  = tid >> 4;
    const int t0q = it * 64;

    // load Q tile (64 rows x 128)
    #pragma unroll
    for (int r = 0; r < 8; ++r) {
        int f   = tid + r * 256;
        int row = f >> 5;
        int d4  = (f & 31) << 2;
        float4 vq = *(const float4*)(
            q + ((size_t)(b * T_ + t0q + row) * NH_ + h) * HD_ + d4);
        *(float4*)(&Qs[row * QS_STRIDE + d4]) = vq;
    }

    float m_[4], l_[4], o_[4][8];
    #pragma unroll
    for (int i = 0; i < 4; ++i) {
        m_[i] = -INFINITY; l_[i] = 0.f;
        #pragma unroll
        for (int dj = 0; dj < 8; ++dj) o_[i][dj] = 0.f;
    }

    const float scale = 0.08838834764831845f;   // 1/sqrt(128)
    const float L2E   = 1.44269504088896340736f;

    for (int jt = 0; jt <= it; ++jt) {
        const int t0k = jt * 64;
        __syncthreads();   // previous iter done reading Ks/Vs/Ps
        #pragma unroll
        for (int r = 0; r < 8; ++r) {
            int f   = tid + r * 256;
            int row = f >> 5;
            int d4  = (f & 31) << 2;
            size_t base = ((size_t)(b * T_ + t0k + row) * NKV_ + kv) * HD_ + d4;
            *(float4*)(&Ks[row * QS_STRIDE + d4]) = *(const float4*)(k + base);
            *(float4*)(&Vs[row * QS_STRIDE + d4]) = *(const float4*)(v + base);
        }
        __syncthreads();

        // S = Q K^T
        float s[4][4];
        #pragma unroll
        for (int i = 0; i < 4; ++i)
            #pragma unroll
            for (int jj = 0; jj < 4; ++jj) s[i][jj] = 0.f;

        #pragma unroll 4
        for (int d = 0; d < 128; d += 4) {
            float qa[4][4], ka[4][4];
            #pragma unroll
            for (int i = 0; i < 4; ++i)
                *(float4*)(qa[i]) = *(const float4*)(&Qs[(4 * ty + i) * QS_STRIDE + d]);
            #pragma unroll
            for (int jj = 0; jj < 4; ++jj)
                *(float4*)(ka[jj]) = *(const float4*)(&Ks[(tx + 16 * jj) * QS_STRIDE + d]);
            #pragma unroll
            for (int dd = 0; dd < 4; ++dd)
                #pragma unroll
                for (int i = 0; i < 4; ++i)
                    #pragma unroll
                    for (int jj = 0; jj < 4; ++jj)
                        s[i][jj] += qa[i][dd] * ka[jj][dd];
        }

        // scale + causal mask (only diagonal tile needs masking)
        #pragma unroll
        for (int i = 0; i < 4; ++i)
            #pragma unroll
            for (int jj = 0; jj < 4; ++jj) {
                s[i][jj] *= scale;
                if (jt == it && (t0k + tx + 16 * jj) > (t0q + 4 * ty + i))
                    s[i][jj] = -INFINITY;
            }

        // online softmax update
        #pragma unroll
        for (int i = 0; i < 4; ++i) {
            float mloc = fmaxf(fmaxf(s[i][0], s[i][1]), fmaxf(s[i][2], s[i][3]));
            #pragma unroll
            for (int off = 8; off; off >>= 1)
                mloc = fmaxf(mloc, __shfl_xor_sync(0xffffffffu, mloc, off));
            float mnew = fmaxf(m_[i], mloc);
            float es   = exp2f((m_[i] - mnew) * L2E);
            float lsum = 0.f;
            #pragma unroll
            for (int jj = 0; jj < 4; ++jj) {
                float p = exp2f((s[i][jj] - mnew) * L2E);
                Ps[(4 * ty + i) * PS_STRIDE + tx + 16 * jj] = p;
                lsum += p;
            }
            #pragma unroll
            for (int off = 8; off; off >>= 1)
                lsum += __shfl_xor_sync(0xffffffffu, lsum, off);
            l_[i] = l_[i] * es + lsum;
            m_[i] = mnew;
            #pragma unroll
            for (int dj = 0; dj < 8; ++dj) o_[i][dj] *= es;
        }
        __syncthreads();   // Ps visible

        // O += P V
        #pragma unroll 4
        for (int ss_ = 0; ss_ < 64; ++ss_) {
            float pv[4], vvr[8];
            #pragma unroll
            for (int i = 0; i < 4; ++i)
                pv[i] = Ps[(4 * ty + i) * PS_STRIDE + ss_];
            #pragma unroll
            for (int dj = 0; dj < 8; ++dj)
                vvr[dj] = Vs[ss_ * QS_STRIDE + tx + 16 * dj];
            #pragma unroll
            for (int i = 0; i < 4; ++i)
                #pragma unroll
                for (int dj = 0; dj < 8; ++dj)
                    o_[i][dj] += pv[i] * vvr[dj];
        }
    }

    // epilogue: normalize and write y (B,T,NH,HD)
    #pragma unroll
    for (int i = 0; i < 4; ++i) {
        float inv = 1.f / l_[i];
        int row = t0q + 4 * ty + i;
        size_t base = ((size_t)(b * T_ + row) * NH_ + h) * HD_;
        #pragma unroll
        for (int dj = 0; dj < 8; ++dj)
            y[base + tx + 16 * dj] = o_[i][dj] * inv;
    }
}

// ---------------------------------------------------------------------------
extern "C" void kernel_launch(void* const* d_in, const int* in_sizes, int n_in,
                              void* d_out, int out_size)
{
    const float* x  = (const float*)d_in[0];
    const float* Wq = (const float*)d_in[1];
    const float* Wk = (const float*)d_in[2];
    const float* Wv = (const float*)d_in[3];
    const float* Wp = (const float*)d_in[4];
    const float* qg = (const float*)d_in[5];
    float* out = (float*)d_out;

    float *q, *kk, *vv, *y;
    cudaGetSymbolAddress((void**)&q,  g_q);
    cudaGetSymbolAddress((void**)&kk, g_k);
    cudaGetSymbolAddress((void**)&vv, g_v);
    cudaGetSymbolAddress((void**)&y,  g_y);

    // 1) RoPE tables
    rope_table_kernel<<<(T_ * 64 + 255) / 256, 256>>>();

    // 2) projections
    dim3 gq(DIM_ / 128, (B_ * T_) / 128);   // (16,32)
    dim3 gk(KD_  / 128, (B_ * T_) / 128);   // (4,32)
    sgemm_nt<<<gq, 256>>>(x, Wq, q,  B_ * T_, DIM_, DIM_);
    sgemm_nt<<<gk, 256>>>(x, Wk, kk, B_ * T_, KD_,  DIM_);
    sgemm_nt<<<gk, 256>>>(x, Wv, vv, B_ * T_, KD_,  DIM_);

    // 3) RMSNorm + RoPE (+gain for q)
    norm_rope_kernel<<<(B_ * T_ * NH_  * 32) / 256, 256>>>(q,  qg,      NH_);
    norm_rope_kernel<<<(B_ * T_ * NKV_ * 32) / 256, 256>>>(kk, nullptr, NKV_);

    // 4) causal GQA flash attention
    size_t shmem = (size_t)(3 * 64 * QS_STRIDE + 64 * PS_STRIDE) * sizeof(float);
    cudaFuncSetAttribute(flash_kernel,
                         cudaFuncAttributeMaxDynamicSharedMemorySize, (int)shmem);
    flash_kernel<<<dim3(T_ / 64, NH_, B_), 256, shmem>>>(q, kk, vv, y);

    // 5) output projection -> d_out
    sgemm_nt<<<gq, 256>>>(y, Wp, out, B_ * T_, DIM_, DIM_);
}

// round 3
// speedup vs baseline: 2.5618x; 2.5618x over previous
#include <cuda_runtime.h>
#include <cuda_bf16.h>
#include <math.h>
#include <stdint.h>

#define B_    2
#define T_    2048
#define DIM_  2048
#define NH_   16
#define NKV_  4
#define HD_   128
#define KD_   512
#define GQ_   (NH_ / NKV_)
#define EPS_  1.1920928955078125e-07f

// ---------------- scratch ----------------------------------------------------
__device__ float g_q[(size_t)B_ * T_ * DIM_];   // (B,T,NH,HD)
__device__ float g_k[(size_t)B_ * T_ * KD_];    // (B,T,NKV,HD)
__device__ float g_v[(size_t)B_ * T_ * KD_];    // (B,T,NKV,HD)
__device__ float g_y[(size_t)B_ * T_ * DIM_];   // attention output (B,T,NH,HD)
__device__ float g_cos[T_ * (HD_ / 2)];
__device__ float g_sin[T_ * (HD_ / 2)];

// ---------------- helpers ----------------------------------------------------
__device__ __forceinline__ uint32_t smem_u32(const void* p) {
    uint32_t a;
    asm("{ .reg .u64 t; cvta.to.shared.u64 t, %1; cvt.u32.u64 %0, t; }"
        : "=r"(a) : "l"(p));
    return a;
}
__device__ __forceinline__ void mma_bf16(float* d, const uint32_t* a, const uint32_t* b) {
    asm volatile("mma.sync.aligned.m16n8k16.row.col.f32.bf16.bf16.f32 "
        "{%0,%1,%2,%3}, {%4,%5,%6,%7}, {%8,%9}, {%0,%1,%2,%3};"
        : "+f"(d[0]), "+f"(d[1]), "+f"(d[2]), "+f"(d[3])
        : "r"(a[0]), "r"(a[1]), "r"(a[2]), "r"(a[3]), "r"(b[0]), "r"(b[1]));
}
__device__ __forceinline__ void ldsm_x4(uint32_t* r, uint32_t addr) {
    asm volatile("ldmatrix.sync.aligned.m8n8.x4.shared.b16 {%0,%1,%2,%3}, [%4];"
        : "=r"(r[0]), "=r"(r[1]), "=r"(r[2]), "=r"(r[3]) : "r"(addr));
}
__device__ __forceinline__ void ldsm_x2(uint32_t* r, uint32_t addr) {
    asm volatile("ldmatrix.sync.aligned.m8n8.x2.shared.b16 {%0,%1}, [%2];"
        : "=r"(r[0]), "=r"(r[1]) : "r"(addr));
}
__device__ __forceinline__ void ldsm_x2_t(uint32_t* r, uint32_t addr) {
    asm volatile("ldmatrix.sync.aligned.m8n8.x2.trans.shared.b16 {%0,%1}, [%2];"
        : "=r"(r[0]), "=r"(r[1]) : "r"(addr));
}
// split float4 -> hi bf16x2 pair + lo bf16x2 pair (8 bytes each)
__device__ __forceinline__ void split4(float4 f, uint2& hi, uint2& lo) {
    __nv_bfloat162 h0 = __floats2bfloat162_rn(f.x, f.y);
    __nv_bfloat162 h1 = __floats2bfloat162_rn(f.z, f.w);
    float2 g0 = __bfloat1622float2(h0), g1 = __bfloat1622float2(h1);
    __nv_bfloat162 l0 = __floats2bfloat162_rn(f.x - g0.x, f.y - g0.y);
    __nv_bfloat162 l1 = __floats2bfloat162_rn(f.z - g1.x, f.w - g1.y);
    hi.x = *(uint32_t*)&h0; hi.y = *(uint32_t*)&h1;
    lo.x = *(uint32_t*)&l0; lo.y = *(uint32_t*)&l1;
}
#define NEG_INF __int_as_float(0xff800000)

// ---------------- RoPE tables ------------------------------------------------
__global__ void rope_table_kernel() {
    int idx = blockIdx.x * blockDim.x + threadIdx.x;
    if (idx >= T_ * (HD_ / 2)) return;
    int t = idx >> 6;
    int i = idx & 63;
    double base = 10000.0;
    if (T_ > 1024)
        base = 10000.0 * pow((double)T_ / 1024.0, (double)HD_ / (double)(HD_ - 2));
    double f = pow(base, -((double)(2 * i)) / (double)HD_);
    double a = (double)t * f;
    g_cos[idx] = (float)cos(a);
    g_sin[idx] = (float)sin(a);
}

// ---------------- RMSNorm + RoPE (+gain) -------------------------------------
__global__ void norm_rope_kernel(float* __restrict__ data,
                                 const float* __restrict__ gain, int nheads)
{
    int gw   = (blockIdx.x * blockDim.x + threadIdx.x) >> 5;
    int lane = threadIdx.x & 31;
    int h = gw % nheads;
    int t = (gw / nheads) % T_;

    float4 v = *(const float4*)(data + (size_t)gw * HD_ + lane * 4);
    float ss = v.x * v.x + v.y * v.y + v.z * v.z + v.w * v.w;
    #pragma unroll
    for (int off = 16; off; off >>= 1)
        ss += __shfl_xor_sync(0xffffffffu, ss, off);
    float r = rsqrtf(ss * (1.f / HD_) + EPS_);

    float x[4] = { v.x * r, v.y * r, v.z * r, v.w * r };
    bool hi = lane >= 16;
    float g = gain ? gain[h] : 1.f;

    float out[4];
    #pragma unroll
    for (int j = 0; j < 4; ++j) {
        float p = __shfl_xor_sync(0xffffffffu, x[j], 16);
        int i   = (lane & 15) * 4 + j;
        float c = g_cos[t * 64 + i];
        float s = g_sin[t * 64 + i];
        out[j] = (hi ? (x[j] * c - p * s) : (x[j] * c + p * s)) * g;
    }
    *(float4*)(data + (size_t)gw * HD_ + lane * 4) =
        make_float4(out[0], out[1], out[2], out[3]);
}

// ---------------- mma.sync GEMM: C[M,N] = A[M,K] * B[N,K]^T -------------------
// fp32 in, split to bf16 hi/lo in-kernel, 3-term compensation.
// 128x128 tile, BK=64, 256 threads (8 warps as 2m x 4n), double-buffered smem.
#define GA_STRIDE 144                 // bytes per smem row (64 bf16 + pad)
#define GTILE_B   (128 * GA_STRIDE)   // 18432
#define GSTAGE_B  (4 * GTILE_B)       // Ah, Al, Bh, Bl = 73728
#define GSMEM_B   (2 * GSTAGE_B)      // 147456

__global__ void __launch_bounds__(256, 1) gemm_mma(
    const float* __restrict__ A, const float* __restrict__ B,
    float* __restrict__ C, int M, int N, int K)
{
    extern __shared__ char sm[];
    const uint32_t sb = smem_u32(sm);
    const int tid = threadIdx.x, wid = tid >> 5, lane = tid & 31;
    const int wm = wid & 1, wn = wid >> 1;
    const int bm = blockIdx.y * 128, bn = blockIdx.x * 128;

    float acc[4][4][4];
    #pragma unroll
    for (int i = 0; i < 4; ++i)
        #pragma unroll
        for (int j = 0; j < 4; ++j)
            #pragma unroll
            for (int q = 0; q < 4; ++q) acc[i][j][q] = 0.f;

    const int niter = K / 64;

    auto load_stage = [&](int it, int buf) {
        const int k0 = it * 64;
        char* s = sm + buf * GSTAGE_B;
        #pragma unroll
        for (int p = 0; p < 16; ++p) {
            int idx  = tid + p * 256;          // 0..4095
            int tile = idx >> 11;              // 0=A, 1=B
            int r    = (idx >> 4) & 127;
            int c4   = idx & 15;
            const float* src = tile ? B : A;
            int rowg = (tile ? bn : bm) + r;
            float4 f = *(const float4*)(src + (size_t)rowg * K + k0 + c4 * 4);
            uint2 hi, lo; split4(f, hi, lo);
            char* dh = s + (tile * 2) * GTILE_B + r * GA_STRIDE + c4 * 8;
            *(uint2*)dh = hi;
            *(uint2*)(dh + GTILE_B) = lo;
        }
    };

    load_stage(0, 0);
    __syncthreads();

    for (int it = 0; it < niter; ++it) {
        const int buf = it & 1;
        const uint32_t sbuf = sb + buf * GSTAGE_B;
        #pragma unroll
        for (int ks = 0; ks < 4; ++ks) {
            uint32_t ah[4][4], al[4][4], bh[4][2], bl[4][2];
            #pragma unroll
            for (int mt = 0; mt < 4; ++mt) {
                uint32_t ra = sbuf + (wm * 64 + mt * 16 + (lane & 15)) * GA_STRIDE
                            + ks * 32 + ((lane >> 4) << 4);
                ldsm_x4(ah[mt], ra);
                ldsm_x4(al[mt], ra + GTILE_B);
            }
            #pragma unroll
            for (int nt = 0; nt < 4; ++nt) {
                uint32_t rb = sbuf + 2 * GTILE_B
                            + (wn * 32 + nt * 8 + (lane & 7)) * GA_STRIDE
                            + ks * 32 + ((lane & 8) << 1);
                ldsm_x2(bh[nt], rb);
                ldsm_x2(bl[nt], rb + GTILE_B);
            }
            #pragma unroll
            for (int mt = 0; mt < 4; ++mt)
                #pragma unroll
                for (int nt = 0; nt < 4; ++nt) {
                    mma_bf16(acc[mt][nt], ah[mt], bh[nt]);
                    mma_bf16(acc[mt][nt], ah[mt], bl[nt]);
                    mma_bf16(acc[mt][nt], al[mt], bh[nt]);
                }
        }
        if (it + 1 < niter) load_stage(it + 1, buf ^ 1);
        __syncthreads();
    }

    #pragma unroll
    for (int mt = 0; mt < 4; ++mt)
        #pragma unroll
        for (int nt = 0; nt < 4; ++nt) {
            int row = bm + wm * 64 + mt * 16 + (lane >> 2);
            int col = bn + wn * 32 + nt * 8 + 2 * (lane & 3);
            *(float2*)(C + (size_t)row * N + col) =
                make_float2(acc[mt][nt][0], acc[mt][nt][1]);
            *(float2*)(C + (size_t)(row + 8) * N + col) =
                make_float2(acc[mt][nt][2], acc[mt][nt][3]);
        }
}

// ---------------- mma.sync causal flash attention -----------------------------
// Q tile 128 rows, KV tile 64 keys. 8 warps; warp w owns Q rows [16w,16w+16).
// Q,K hi/lo (3-term QK), P hi/lo x V hi/lo (3-term PV). fp32 softmax.
#define FQ_STRIDE 272                 // 128 bf16 + pad
#define QTILE_B (128 * FQ_STRIDE)     // 34816
#define KTILE_B (64 * FQ_STRIDE)      // 17408
// layout: Qh | Ql | Kh | Kl | Vh | Vl
#define OFF_Q  0
#define OFF_K  (2 * QTILE_B)
#define OFF_V  (2 * QTILE_B + 2 * KTILE_B)
#define FSMEM  (2 * QTILE_B + 4 * KTILE_B)   // 139264

__global__ void __launch_bounds__(256, 1) flash_mma(
    const float* __restrict__ q, const float* __restrict__ k,
    const float* __restrict__ v, float* __restrict__ y)
{
    extern __shared__ char sm[];
    const uint32_t sb = smem_u32(sm);
    const int tid = threadIdx.x, wid = tid >> 5, lane = tid & 31;
    const int it = blockIdx.x, h = blockIdx.y, b = blockIdx.z;
    const int kvh = h / GQ_;
    const int t0q = it * 128;
    const float scale = 0.08838834764831845f;   // 1/sqrt(128)
    const float L2E   = 1.44269504088896340736f;

    // load Q tile (128 x 128 fp32) -> Qh/Ql
    #pragma unroll
    for (int p = 0; p < 16; ++p) {
        int idx = tid + p * 256;
        int r = idx >> 5, c4 = idx & 31;
        float4 f = *(const float4*)(
            q + ((size_t)(b * T_ + t0q + r) * NH_ + h) * HD_ + c4 * 4);
        uint2 hi, lo; split4(f, hi, lo);
        char* dh = sm + OFF_Q + r * FQ_STRIDE + c4 * 8;
        *(uint2*)dh = hi;
        *(uint2*)(dh + QTILE_B) = lo;
    }

    float m0 = NEG_INF, m1 = NEG_INF, l0 = 0.f, l1 = 0.f;
    float O[16][4];
    #pragma unroll
    for (int nt = 0; nt < 16; ++nt)
        #pragma unroll
        for (int j = 0; j < 4; ++j) O[nt][j] = 0.f;

    const int row_a = t0q + wid * 16 + (lane >> 2);  // global q row (lo)
    const int jmax  = 2 * it + 1;

    for (int jt = 0; jt <= jmax; ++jt) {
        const int t0k = jt * 64;
        __syncthreads();
        // load K,V tiles (64 x 128 fp32 each)
        #pragma unroll
        for (int p = 0; p < 16; ++p) {
            int idx = tid + p * 256;
            int tensor = idx >> 11;               // 0=K, 1=V
            int r = (idx >> 5) & 63, c4 = idx & 31;
            const float* src = tensor ? v : k;
            float4 f = *(const float4*)(
                src + ((size_t)(b * T_ + t0k + r) * NKV_ + kvh) * HD_ + c4 * 4);
            uint2 hi, lo; split4(f, hi, lo);
            char* dh = sm + OFF_K + tensor * 2 * KTILE_B + r * FQ_STRIDE + c4 * 8;
            *(uint2*)dh = hi;
            *(uint2*)(dh + KTILE_B) = lo;
        }
        __syncthreads();

        // ---- S = Q K^T (3-term) ----
        float S[8][4];
        #pragma unroll
        for (int nt = 0; nt < 8; ++nt)
            #pragma unroll
            for (int j = 0; j < 4; ++j) S[nt][j] = 0.f;

        #pragma unroll
        for (int ks = 0; ks < 8; ++ks) {
            uint32_t ah[4], al[4];
            uint32_t ra = sb + OFF_Q + (wid * 16 + (lane & 15)) * FQ_STRIDE
                        + ks * 32 + ((lane >> 4) << 4);
            ldsm_x4(ah, ra);
            ldsm_x4(al, ra + QTILE_B);
            #pragma unroll
            for (int nt = 0; nt < 8; ++nt) {
                uint32_t bh[2], bl[2];
                uint32_t rb = sb + OFF_K + (nt * 8 + (lane & 7)) * FQ_STRIDE
                            + ks * 32 + ((lane & 8) << 1);
                ldsm_x2(bh, rb);
                ldsm_x2(bl, rb + KTILE_B);
                mma_bf16(S[nt], ah, bh);
                mma_bf16(S[nt], ah, bl);
                mma_bf16(S[nt], al, bh);
            }
        }

        // ---- scale + causal mask + online softmax ----
        const bool diag = (jt >= 2 * it);
        float ml0 = NEG_INF, ml1 = NEG_INF;
        #pragma unroll
        for (int nt = 0; nt < 8; ++nt) {
            int c = t0k + nt * 8 + 2 * (lane & 3);
            #pragma unroll
            for (int j = 0; j < 4; ++j) S[nt][j] *= scale;
            if (diag) {
                if (c     > row_a)     S[nt][0] = NEG_INF;
                if (c + 1 > row_a)     S[nt][1] = NEG_INF;
                if (c     > row_a + 8) S[nt][2] = NEG_INF;
                if (c + 1 > row_a + 8) S[nt][3] = NEG_INF;
            }
            ml0 = fmaxf(ml0, fmaxf(S[nt][0], S[nt][1]));
            ml1 = fmaxf(ml1, fmaxf(S[nt][2], S[nt][3]));
        }
        ml0 = fmaxf(ml0, __shfl_xor_sync(0xffffffffu, ml0, 1));
        ml0 = fmaxf(ml0, __shfl_xor_sync(0xffffffffu, ml0, 2));
        ml1 = fmaxf(ml1, __shfl_xor_sync(0xffffffffu, ml1, 1));
        ml1 = fmaxf(ml1, __shfl_xor_sync(0xffffffffu, ml1, 2));

        float mn0 = fmaxf(m0, ml0), mn1 = fmaxf(m1, ml1);
        float es0 = exp2f((m0 - mn0) * L2E);
        float es1 = exp2f((m1 - mn1) * L2E);
        m0 = mn0; m1 = mn1;

        float sum0 = 0.f, sum1 = 0.f;
        uint32_t PH[16], PL[16];
        #pragma unroll
        for (int nt = 0; nt < 8; ++nt) {
            float p0 = exp2f((S[nt][0] - mn0) * L2E);
            float p1 = exp2f((S[nt][1] - mn0) * L2E);
            float p2 = exp2f((S[nt][2] - mn1) * L2E);
            float p3 = exp2f((S[nt][3] - mn1) * L2E);
            sum0 += p0 + p1;  sum1 += p2 + p3;
            __nv_bfloat162 hA = __floats2bfloat162_rn(p0, p1);
            __nv_bfloat162 hB = __floats2bfloat162_rn(p2, p3);
            float2 gA = __bfloat1622float2(hA), gB = __bfloat1622float2(hB);
            __nv_bfloat162 lA = __floats2bfloat162_rn(p0 - gA.x, p1 - gA.y);
            __nv_bfloat162 lB = __floats2bfloat162_rn(p2 - gB.x, p3 - gB.y);
            PH[2 * nt]     = *(uint32_t*)&hA;
            PH[2 * nt + 1] = *(uint32_t*)&hB;
            PL[2 * nt]     = *(uint32_t*)&lA;
            PL[2 * nt + 1] = *(uint32_t*)&lB;
        }
        sum0 += __shfl_xor_sync(0xffffffffu, sum0, 1);
        sum0 += __shfl_xor_sync(0xffffffffu, sum0, 2);
        sum1 += __shfl_xor_sync(0xffffffffu, sum1, 1);
        sum1 += __shfl_xor_sync(0xffffffffu, sum1, 2);
        l0 = l0 * es0 + sum0;
        l1 = l1 * es1 + sum1;
        #pragma unroll
        for (int nt = 0; nt < 16; ++nt) {
            O[nt][0] *= es0; O[nt][1] *= es0;
            O[nt][2] *= es1; O[nt][3] *= es1;
        }

        // ---- O += P V (3-term) ----
        #pragma unroll
        for (int kt = 0; kt < 4; ++kt) {
            uint32_t pa[4] = { PH[4*kt], PH[4*kt+1], PH[4*kt+2], PH[4*kt+3] };
            uint32_t pl[4] = { PL[4*kt], PL[4*kt+1], PL[4*kt+2], PL[4*kt+3] };
            uint32_t vrow = sb + OFF_V + (kt * 16 + (lane & 15)) * FQ_STRIDE;
            #pragma unroll
            for (int nt = 0; nt < 16; ++nt) {
                uint32_t bh[2], bl[2];
                ldsm_x2_t(bh, vrow + nt * 16);
                ldsm_x2_t(bl, vrow + nt * 16 + KTILE_B);
                mma_bf16(O[nt], pa, bh);
                mma_bf16(O[nt], pa, bl);
                mma_bf16(O[nt], pl, bh);
            }
        }
    }

    // ---- epilogue ----
    float inv0 = 1.f / l0, inv1 = 1.f / l1;
    #pragma unroll
    for (int nt = 0; nt < 16; ++nt) {
        int c = nt * 8 + 2 * (lane & 3);
        size_t baseA = ((size_t)(b * T_ + row_a) * NH_ + h) * HD_ + c;
        size_t baseB = ((size_t)(b * T_ + row_a + 8) * NH_ + h) * HD_ + c;
        *(float2*)(y + baseA) = make_float2(O[nt][0] * inv0, O[nt][1] * inv0);
        *(float2*)(y + baseB) = make_float2(O[nt][2] * inv1, O[nt][3] * inv1);
    }
}

// ---------------------------------------------------------------------------
extern "C" void kernel_launch(void* const* d_in, const int* in_sizes, int n_in,
                              void* d_out, int out_size)
{
    const float* x  = (const float*)d_in[0];
    const float* Wq = (const float*)d_in[1];
    const float* Wk = (const float*)d_in[2];
    const float* Wv = (const float*)d_in[3];
    const float* Wp = (const float*)d_in[4];
    const float* qg = (const float*)d_in[5];
    float* out = (float*)d_out;

    float *q, *kk, *vv, *y;
    cudaGetSymbolAddress((void**)&q,  g_q);
    cudaGetSymbolAddress((void**)&kk, g_k);
    cudaGetSymbolAddress((void**)&vv, g_v);
    cudaGetSymbolAddress((void**)&y,  g_y);

    // 1) RoPE tables
    rope_table_kernel<<<(T_ * 64 + 255) / 256, 256>>>();

    // 2) projections (tensor cores via mma.sync)
    cudaFuncSetAttribute(gemm_mma, cudaFuncAttributeMaxDynamicSharedMemorySize, GSMEM_B);
    dim3 gq(DIM_ / 128, (B_ * T_) / 128);   // (16,32)
    dim3 gk(KD_  / 128, (B_ * T_) / 128);   // (4,32)
    gemm_mma<<<gq, 256, GSMEM_B>>>(x, Wq, q,  B_ * T_, DIM_, DIM_);
    gemm_mma<<<gk, 256, GSMEM_B>>>(x, Wk, kk, B_ * T_, KD_,  DIM_);
    gemm_mma<<<gk, 256, GSMEM_B>>>(x, Wv, vv, B_ * T_, KD_,  DIM_);

    // 3) RMSNorm + RoPE (+gain for q)
    norm_rope_kernel<<<(B_ * T_ * NH_  * 32) / 256, 256>>>(q,  qg,      NH_);
    norm_rope_kernel<<<(B_ * T_ * NKV_ * 32) / 256, 256>>>(kk, nullptr, NKV_);

    // 4) causal GQA flash attention (mma.sync)
    cudaFuncSetAttribute(flash_mma, cudaFuncAttributeMaxDynamicSharedMemorySize, FSMEM);
    flash_mma<<<dim3(T_ / 128, NH_, B_), 256, FSMEM>>>(q, kk, vv, y);

    // 5) output projection
    gemm_mma<<<gq, 256, GSMEM_B>>>(y, Wp, out, B_ * T_, DIM_, DIM_);
}

// round 4
// speedup vs baseline: 2.5933x; 1.0123x over previous
#include <cuda_runtime.h>
#include <cuda_bf16.h>
#include <math.h>
#include <stdint.h>

#define B_    2
#define T_    2048
#define DIM_  2048
#define NH_   16
#define NKV_  4
#define HD_   128
#define KD_   512
#define GQ_   (NH_ / NKV_)
#define EPS_  1.1920928955078125e-07f

// ---------------- scratch ----------------------------------------------------
__device__ float g_q[(size_t)B_ * T_ * DIM_];   // fp32 q (pre-norm)
__device__ float g_k[(size_t)B_ * T_ * KD_];    // fp32 k (pre-norm)
__device__ float g_v[(size_t)B_ * T_ * KD_];    // fp32 v
__device__ float g_y[(size_t)B_ * T_ * DIM_];   // attention output
__device__ float g_cos[T_ * (HD_ / 2)];
__device__ float g_sin[T_ * (HD_ / 2)];
// bf16 hi/lo post-norm/rope buffers for flash
__device__ __nv_bfloat16 g_qh[(size_t)B_ * T_ * DIM_];
__device__ __nv_bfloat16 g_ql[(size_t)B_ * T_ * DIM_];
__device__ __nv_bfloat16 g_kh[(size_t)B_ * T_ * KD_];
__device__ __nv_bfloat16 g_kl[(size_t)B_ * T_ * KD_];
__device__ __nv_bfloat16 g_vh[(size_t)B_ * T_ * KD_];
__device__ __nv_bfloat16 g_vl[(size_t)B_ * T_ * KD_];

// ---------------- helpers ----------------------------------------------------
__device__ __forceinline__ uint32_t smem_u32(const void* p) {
    uint32_t a;
    asm("{ .reg .u64 t; cvta.to.shared.u64 t, %1; cvt.u32.u64 %0, t; }"
        : "=r"(a) : "l"(p));
    return a;
}
__device__ __forceinline__ void mma_bf16(float* d, const uint32_t* a, const uint32_t* b) {
    asm volatile("mma.sync.aligned.m16n8k16.row.col.f32.bf16.bf16.f32 "
        "{%0,%1,%2,%3}, {%4,%5,%6,%7}, {%8,%9}, {%0,%1,%2,%3};"
        : "+f"(d[0]), "+f"(d[1]), "+f"(d[2]), "+f"(d[3])
        : "r"(a[0]), "r"(a[1]), "r"(a[2]), "r"(a[3]), "r"(b[0]), "r"(b[1]));
}
__device__ __forceinline__ void ldsm_x4(uint32_t* r, uint32_t addr) {
    asm volatile("ldmatrix.sync.aligned.m8n8.x4.shared.b16 {%0,%1,%2,%3}, [%4];"
        : "=r"(r[0]), "=r"(r[1]), "=r"(r[2]), "=r"(r[3]) : "r"(addr));
}
__device__ __forceinline__ void ldsm_x2(uint32_t* r, uint32_t addr) {
    asm volatile("ldmatrix.sync.aligned.m8n8.x2.shared.b16 {%0,%1}, [%2];"
        : "=r"(r[0]), "=r"(r[1]) : "r"(addr));
}
__device__ __forceinline__ void ldsm_x4_t(uint32_t* r, uint32_t addr) {
    asm volatile("ldmatrix.sync.aligned.m8n8.x4.trans.shared.b16 {%0,%1,%2,%3}, [%4];"
        : "=r"(r[0]), "=r"(r[1]), "=r"(r[2]), "=r"(r[3]) : "r"(addr));
}
__device__ __forceinline__ void cp16(uint32_t dst, const void* src) {
    asm volatile("cp.async.cg.shared.global [%0], [%1], 16;" :: "r"(dst), "l"(src));
}
#define CP_COMMIT() asm volatile("cp.async.commit_group;" ::: "memory")
#define CP_WAIT0()  asm volatile("cp.async.wait_group 0;" ::: "memory")

// split float4 -> hi bf16x2 pair + lo bf16x2 pair
__device__ __forceinline__ void split4(float4 f, uint2& hi, uint2& lo) {
    __nv_bfloat162 h0 = __floats2bfloat162_rn(f.x, f.y);
    __nv_bfloat162 h1 = __floats2bfloat162_rn(f.z, f.w);
    float2 g0 = __bfloat1622float2(h0), g1 = __bfloat1622float2(h1);
    __nv_bfloat162 l0 = __floats2bfloat162_rn(f.x - g0.x, f.y - g0.y);
    __nv_bfloat162 l1 = __floats2bfloat162_rn(f.z - g1.x, f.w - g1.y);
    hi.x = *(uint32_t*)&h0; hi.y = *(uint32_t*)&h1;
    lo.x = *(uint32_t*)&l0; lo.y = *(uint32_t*)&l1;
}
#define NEG_INF __int_as_float(0xff800000)

// ---------------- RoPE tables ------------------------------------------------
__global__ void rope_table_kernel() {
    int idx = blockIdx.x * blockDim.x + threadIdx.x;
    if (idx >= T_ * (HD_ / 2)) return;
    int t = idx >> 6;
    int i = idx & 63;
    double base = 10000.0;
    if (T_ > 1024)
        base = 10000.0 * pow((double)T_ / 1024.0, (double)HD_ / (double)(HD_ - 2));
    double f = pow(base, -((double)(2 * i)) / (double)HD_);
    double a = (double)t * f;
    g_cos[idx] = (float)cos(a);
    g_sin[idx] = (float)sin(a);
}

// ---------------- RMSNorm + RoPE (+gain) -> bf16 hi/lo -----------------------
__global__ void norm_rope_kernel(const float* __restrict__ data,
                                 const float* __restrict__ gain, int nheads,
                                 __nv_bfloat16* __restrict__ oh,
                                 __nv_bfloat16* __restrict__ ol)
{
    int gw   = (blockIdx.x * blockDim.x + threadIdx.x) >> 5;
    int lane = threadIdx.x & 31;
    int h = gw % nheads;
    int t = (gw / nheads) % T_;

    float4 v = *(const float4*)(data + (size_t)gw * HD_ + lane * 4);
    float ss = v.x * v.x + v.y * v.y + v.z * v.z + v.w * v.w;
    #pragma unroll
    for (int off = 16; off; off >>= 1)
        ss += __shfl_xor_sync(0xffffffffu, ss, off);
    float r = rsqrtf(ss * (1.f / HD_) + EPS_);

    float x[4] = { v.x * r, v.y * r, v.z * r, v.w * r };
    bool hi = lane >= 16;
    float g = gain ? gain[h] : 1.f;

    float out[4];
    #pragma unroll
    for (int j = 0; j < 4; ++j) {
        float p = __shfl_xor_sync(0xffffffffu, x[j], 16);
        int i   = (lane & 15) * 4 + j;
        float c = g_cos[t * 64 + i];
        float s = g_sin[t * 64 + i];
        out[j] = (hi ? (x[j] * c - p * s) : (x[j] * c + p * s)) * g;
    }
    uint2 hh, ll;
    split4(make_float4(out[0], out[1], out[2], out[3]), hh, ll);
    *(uint2*)(oh + (size_t)gw * HD_ + lane * 4) = hh;
    *(uint2*)(ol + (size_t)gw * HD_ + lane * 4) = ll;
}

// ---------------- fp32 -> bf16 hi/lo split (for V) ---------------------------
__global__ void split_kernel(const float* __restrict__ src,
                             __nv_bfloat16* __restrict__ hi,
                             __nv_bfloat16* __restrict__ lo, int n4) {
    int i = blockIdx.x * blockDim.x + threadIdx.x;
    if (i >= n4) return;
    float4 f = ((const float4*)src)[i];
    uint2 h, l; split4(f, h, l);
    ((uint2*)hi)[i] = h;
    ((uint2*)lo)[i] = l;
}

// ---------------- mma.sync GEMM body ------------------------------------------
#define GA_STRIDE 144
#define GTILE_B   (128 * GA_STRIDE)
#define GSTAGE_B  (4 * GTILE_B)
#define GSMEM_B   (2 * GSTAGE_B)

__device__ __forceinline__ void gemm_body(
    const float* __restrict__ A, const float* __restrict__ Bm,
    float* __restrict__ C, int M, int N, int K, int bm, int bn)
{
    extern __shared__ char sm[];
    const uint32_t sb = smem_u32(sm);
    const int tid = threadIdx.x, wid = tid >> 5, lane = tid & 31;
    const int wm = wid & 1, wn = wid >> 1;

    float acc[4][4][4];
    #pragma unroll
    for (int i = 0; i < 4; ++i)
        #pragma unroll
        for (int j = 0; j < 4; ++j)
            #pragma unroll
            for (int q = 0; q < 4; ++q) acc[i][j][q] = 0.f;

    const int niter = K / 64;

    auto load_stage = [&](int it, int buf) {
        const int k0 = it * 64;
        char* s = sm + buf * GSTAGE_B;
        #pragma unroll
        for (int p = 0; p < 16; ++p) {
            int idx  = tid + p * 256;
            int tile = idx >> 11;
            int r    = (idx >> 4) & 127;
            int c4   = idx & 15;
            const float* src = tile ? Bm : A;
            int rowg = (tile ? bn : bm) + r;
            float4 f = *(const float4*)(src + (size_t)rowg * K + k0 + c4 * 4);
            uint2 hi, lo; split4(f, hi, lo);
            char* dh = s + (tile * 2) * GTILE_B + r * GA_STRIDE + c4 * 8;
            *(uint2*)dh = hi;
            *(uint2*)(dh + GTILE_B) = lo;
        }
    };

    load_stage(0, 0);
    __syncthreads();

    for (int it = 0; it < niter; ++it) {
        const int buf = it & 1;
        const uint32_t sbuf = sb + buf * GSTAGE_B;
        #pragma unroll
        for (int ks = 0; ks < 4; ++ks) {
            uint32_t ah[4][4], al[4][4], bh[4][2], bl[4][2];
            #pragma unroll
            for (int mt = 0; mt < 4; ++mt) {
                uint32_t ra = sbuf + (wm * 64 + mt * 16 + (lane & 15)) * GA_STRIDE
                            + ks * 32 + ((lane >> 4) << 4);
                ldsm_x4(ah[mt], ra);
                ldsm_x4(al[mt], ra + GTILE_B);
            }
            #pragma unroll
            for (int nt = 0; nt < 4; ++nt) {
                uint32_t rb = sbuf + 2 * GTILE_B
                            + (wn * 32 + nt * 8 + (lane & 7)) * GA_STRIDE
                            + ks * 32 + ((lane & 8) << 1);
                ldsm_x2(bh[nt], rb);
                ldsm_x2(bl[nt], rb + GTILE_B);
            }
            #pragma unroll
            for (int mt = 0; mt < 4; ++mt)
                #pragma unroll
                for (int nt = 0; nt < 4; ++nt) {
                    mma_bf16(acc[mt][nt], ah[mt], bh[nt]);
                    mma_bf16(acc[mt][nt], ah[mt], bl[nt]);
                    mma_bf16(acc[mt][nt], al[mt], bh[nt]);
                }
        }
        if (it + 1 < niter) load_stage(it + 1, buf ^ 1);
        __syncthreads();
    }

    #pragma unroll
    for (int mt = 0; mt < 4; ++mt)
        #pragma unroll
        for (int nt = 0; nt < 4; ++nt) {
            int row = bm + wm * 64 + mt * 16 + (lane >> 2);
            int col = bn + wn * 32 + nt * 8 + 2 * (lane & 3);
            *(float2*)(C + (size_t)row * N + col) =
                make_float2(acc[mt][nt][0], acc[mt][nt][1]);
            *(float2*)(C + (size_t)(row + 8) * N + col) =
                make_float2(acc[mt][nt][2], acc[mt][nt][3]);
        }
}

__global__ void __launch_bounds__(256, 1) gemm_mma(
    const float* __restrict__ A, const float* __restrict__ B,
    float* __restrict__ C, int M, int N, int K)
{
    gemm_body(A, B, C, M, N, K, blockIdx.y * 128, blockIdx.x * 128);
}

// fused K+V projections: first half of grid.x -> (B1,C1), second -> (B2,C2)
__global__ void __launch_bounds__(256, 1) gemm_mma2(
    const float* __restrict__ A,
    const float* __restrict__ B1, float* __restrict__ C1,
    const float* __restrict__ B2, float* __restrict__ C2,
    int M, int N, int K)
{
    int half = gridDim.x >> 1;
    if (blockIdx.x < half)
        gemm_body(A, B1, C1, M, N, K, blockIdx.y * 128, blockIdx.x * 128);
    else
        gemm_body(A, B2, C2, M, N, K, blockIdx.y * 128, (blockIdx.x - half) * 128);
}

// ---------------- flash attention: cp.async bf16 hi/lo, x4 ldsm ---------------
// Q tile 128 rows, KV tile 64 keys, 8 warps, double-buffered KV stages.
#define FST    272                    // bytes per smem row (128 bf16 + 16 pad)
#define QT     (128 * FST)            // 34816 per Q part
#define KST    (64 * FST)             // 17408 per KV part
#define STG    (4 * KST)              // Kh|Kl|Vh|Vl = 69632
#define FSMEM  (2 * QT + 2 * STG)     // 208896

__global__ void __launch_bounds__(256, 1) flash_mma(
    const __nv_bfloat16* __restrict__ qh, const __nv_bfloat16* __restrict__ ql,
    const __nv_bfloat16* __restrict__ kh, const __nv_bfloat16* __restrict__ kl,
    const __nv_bfloat16* __restrict__ vh, const __nv_bfloat16* __restrict__ vl,
    float* __restrict__ y)
{
    extern __shared__ char sm[];
    const uint32_t sb = smem_u32(sm);
    const int tid = threadIdx.x, wid = tid >> 5, lane = tid & 31;
    const int itq = (gridDim.x - 1) - blockIdx.x;   // heavy tiles first
    const int h = blockIdx.y, b = blockIdx.z;
    const int kvh = h / GQ_;
    const int t0q = itq * 128;
    const float scale = 0.08838834764831845f;   // 1/sqrt(128)
    const float L2E   = 1.44269504088896340736f;
    const int jmax = 2 * itq + 1;

    // --- async load Q (hi/lo) ---
    #pragma unroll
    for (int p = 0; p < 16; ++p) {
        int idx = tid + p * 256;
        int part = idx >> 11;                // 0=hi,1=lo
        int r = (idx >> 4) & 127;
        int c = idx & 15;
        const __nv_bfloat16* src = part ? ql : qh;
        cp16(sb + part * QT + r * FST + c * 16,
             src + ((size_t)(b * T_ + t0q + r) * NH_ + h) * HD_ + c * 8);
    }
    // --- async load KV stage 0 ---
    {
        #pragma unroll
        for (int p = 0; p < 16; ++p) {
            int idx = tid + p * 256;
            int part = idx >> 10;            // 0..3 : Kh,Kl,Vh,Vl
            int r = (idx >> 4) & 63;
            int c = idx & 15;
            const __nv_bfloat16* src = (part == 0) ? kh : (part == 1) ? kl
                                      : (part == 2) ? vh : vl;
            cp16(sb + 2 * QT + part * KST + r * FST + c * 16,
                 src + ((size_t)(b * T_ + r) * NKV_ + kvh) * HD_ + c * 8);
        }
    }
    CP_COMMIT();

    float m0 = NEG_INF, m1 = NEG_INF, l0 = 0.f, l1 = 0.f;
    float O[16][4];
    #pragma unroll
    for (int nt = 0; nt < 16; ++nt)
        #pragma unroll
        for (int j = 0; j < 4; ++j) O[nt][j] = 0.f;

    const int row_a = t0q + wid * 16 + (lane >> 2);

    for (int jt = 0; jt <= jmax; ++jt) {
        const int buf = jt & 1;
        CP_WAIT0();
        __syncthreads();
        // prefetch next stage into buf^1 (overlaps compute below)
        if (jt + 1 <= jmax) {
            const int t0n = (jt + 1) * 64;
            #pragma unroll
            for (int p = 0; p < 16; ++p) {
                int idx = tid + p * 256;
                int part = idx >> 10;
                int r = (idx >> 4) & 63;
                int c = idx & 15;
                const __nv_bfloat16* src = (part == 0) ? kh : (part == 1) ? kl
                                          : (part == 2) ? vh : vl;
                cp16(sb + 2 * QT + (buf ^ 1) * STG + part * KST + r * FST + c * 16,
                     src + ((size_t)(b * T_ + t0n + r) * NKV_ + kvh) * HD_ + c * 8);
            }
            CP_COMMIT();
        }

        const uint32_t base_kv = sb + 2 * QT + buf * STG;
        const int t0k = jt * 64;

        // ---- S = Q K^T (3-term) ----
        float S[8][4];
        #pragma unroll
        for (int nt = 0; nt < 8; ++nt)
            #pragma unroll
            for (int j = 0; j < 4; ++j) S[nt][j] = 0.f;

        #pragma unroll
        for (int ks = 0; ks < 8; ++ks) {
            uint32_t ah[4], al[4];
            uint32_t ra = sb + (wid * 16 + (lane & 15)) * FST
                        + ks * 32 + ((lane >> 4) << 4);
            ldsm_x4(ah, ra);
            ldsm_x4(al, ra + QT);
            #pragma unroll
            for (int ntp = 0; ntp < 4; ++ntp) {
                uint32_t bh[4], bl[4];
                uint32_t rb = base_kv
                            + (ntp * 16 + (lane & 7) + ((lane >> 4) << 3)) * FST
                            + ks * 32 + (((lane >> 3) & 1) << 4);
                ldsm_x4(bh, rb);
                ldsm_x4(bl, rb + KST);
                mma_bf16(S[2 * ntp],     ah, bh);
                mma_bf16(S[2 * ntp],     ah, bl);
                mma_bf16(S[2 * ntp],     al, bh);
                mma_bf16(S[2 * ntp + 1], ah, bh + 2);
                mma_bf16(S[2 * ntp + 1], ah, bl + 2);
                mma_bf16(S[2 * ntp + 1], al, bh + 2);
            }
        }

        // ---- scale + causal mask + online softmax ----
        const bool diag = (jt >= 2 * itq);
        float ml0 = NEG_INF, ml1 = NEG_INF;
        #pragma unroll
        for (int nt = 0; nt < 8; ++nt) {
            int c = t0k + nt * 8 + 2 * (lane & 3);
            #pragma unroll
            for (int j = 0; j < 4; ++j) S[nt][j] *= scale;
            if (diag) {
                if (c     > row_a)     S[nt][0] = NEG_INF;
                if (c + 1 > row_a)     S[nt][1] = NEG_INF;
                if (c     > row_a + 8) S[nt][2] = NEG_INF;
                if (c + 1 > row_a + 8) S[nt][3] = NEG_INF;
            }
            ml0 = fmaxf(ml0, fmaxf(S[nt][0], S[nt][1]));
            ml1 = fmaxf(ml1, fmaxf(S[nt][2], S[nt][3]));
        }
        ml0 = fmaxf(ml0, __shfl_xor_sync(0xffffffffu, ml0, 1));
        ml0 = fmaxf(ml0, __shfl_xor_sync(0xffffffffu, ml0, 2));
        ml1 = fmaxf(ml1, __shfl_xor_sync(0xffffffffu, ml1, 1));
        ml1 = fmaxf(ml1, __shfl_xor_sync(0xffffffffu, ml1, 2));

        float mn0 = fmaxf(m0, ml0), mn1 = fmaxf(m1, ml1);
        float es0 = exp2f((m0 - mn0) * L2E);
        float es1 = exp2f((m1 - mn1) * L2E);
        m0 = mn0; m1 = mn1;

        float sum0 = 0.f, sum1 = 0.f;
        uint32_t PH[16], PL[16];
        #pragma unroll
        for (int nt = 0; nt < 8; ++nt) {
            float p0 = exp2f((S[nt][0] - mn0) * L2E);
            float p1 = exp2f((S[nt][1] - mn0) * L2E);
            float p2 = exp2f((S[nt][2] - mn1) * L2E);
            float p3 = exp2f((S[nt][3] - mn1) * L2E);
            sum0 += p0 + p1;  sum1 += p2 + p3;
            __nv_bfloat162 hA = __floats2bfloat162_rn(p0, p1);
            __nv_bfloat162 hB = __floats2bfloat162_rn(p2, p3);
            float2 gA = __bfloat1622float2(hA), gB = __bfloat1622float2(hB);
            __nv_bfloat162 lA = __floats2bfloat162_rn(p0 - gA.x, p1 - gA.y);
            __nv_bfloat162 lB = __floats2bfloat162_rn(p2 - gB.x, p3 - gB.y);
            PH[2 * nt]     = *(uint32_t*)&hA;
            PH[2 * nt + 1] = *(uint32_t*)&hB;
            PL[2 * nt]     = *(uint32_t*)&lA;
            PL[2 * nt + 1] = *(uint32_t*)&lB;
        }
        sum0 += __shfl_xor_sync(0xffffffffu, sum0, 1);
        sum0 += __shfl_xor_sync(0xffffffffu, sum0, 2);
        sum1 += __shfl_xor_sync(0xffffffffu, sum1, 1);
        sum1 += __shfl_xor_sync(0xffffffffu, sum1, 2);
        l0 = l0 * es0 + sum0;
        l1 = l1 * es1 + sum1;
        #pragma unroll
        for (int nt = 0; nt < 16; ++nt) {
            O[nt][0] *= es0; O[nt][1] *= es0;
            O[nt][2] *= es1; O[nt][3] *= es1;
        }

        // ---- O += P V (3-term), V frags via x4.trans ----
        const uint32_t base_v = base_kv + 2 * KST;
        #pragma unroll
        for (int kt = 0; kt < 4; ++kt) {
            uint32_t pa[4] = { PH[4*kt], PH[4*kt+1], PH[4*kt+2], PH[4*kt+3] };
            uint32_t pl[4] = { PL[4*kt], PL[4*kt+1], PL[4*kt+2], PL[4*kt+3] };
            #pragma unroll
            for (int ntp = 0; ntp < 8; ++ntp) {
                uint32_t bh[4], bl[4];
                uint32_t rv = base_v
                            + (kt * 16 + (lane & 7) + (lane & 8)) * FST
                            + ntp * 32 + ((lane >> 4) << 4);
                ldsm_x4_t(bh, rv);
                ldsm_x4_t(bl, rv + KST);
                mma_bf16(O[2 * ntp],     pa, bh);
                mma_bf16(O[2 * ntp],     pa, bl);
                mma_bf16(O[2 * ntp],     pl, bh);
                mma_bf16(O[2 * ntp + 1], pa, bh + 2);
                mma_bf16(O[2 * ntp + 1], pa, bl + 2);
                mma_bf16(O[2 * ntp + 1], pl, bh + 2);
            }
        }
    }

    // ---- epilogue ----
    float inv0 = 1.f / l0, inv1 = 1.f / l1;
    #pragma unroll
    for (int nt = 0; nt < 16; ++nt) {
        int c = nt * 8 + 2 * (lane & 3);
        size_t baseA = ((size_t)(b * T_ + row_a) * NH_ + h) * HD_ + c;
        size_t baseB = ((size_t)(b * T_ + row_a + 8) * NH_ + h) * HD_ + c;
        *(float2*)(y + baseA) = make_float2(O[nt][0] * inv0, O[nt][1] * inv0);
        *(float2*)(y + baseB) = make_float2(O[nt][2] * inv1, O[nt][3] * inv1);
    }
}

// ---------------------------------------------------------------------------
extern "C" void kernel_launch(void* const* d_in, const int* in_sizes, int n_in,
                              void* d_out, int out_size)
{
    const float* x  = (const float*)d_in[0];
    const float* Wq = (const float*)d_in[1];
    const float* Wk = (const float*)d_in[2];
    const float* Wv = (const float*)d_in[3];
    const float* Wp = (const float*)d_in[4];
    const float* qg = (const float*)d_in[5];
    float* out = (float*)d_out;

    float *q, *kk, *vv, *y;
    cudaGetSymbolAddress((void**)&q,  g_q);
    cudaGetSymbolAddress((void**)&kk, g_k);
    cudaGetSymbolAddress((void**)&vv, g_v);
    cudaGetSymbolAddress((void**)&y,  g_y);
    __nv_bfloat16 *qh,*ql,*kh,*kl,*vh,*vl;
    cudaGetSymbolAddress((void**)&qh, g_qh); cudaGetSymbolAddress((void**)&ql, g_ql);
    cudaGetSymbolAddress((void**)&kh, g_kh); cudaGetSymbolAddress((void**)&kl, g_kl);
    cudaGetSymbolAddress((void**)&vh, g_vh); cudaGetSymbolAddress((void**)&vl, g_vl);

    // 1) RoPE tables
    rope_table_kernel<<<(T_ * 64 + 255) / 256, 256>>>();

    // 2) projections
    cudaFuncSetAttribute(gemm_mma,  cudaFuncAttributeMaxDynamicSharedMemorySize, GSMEM_B);
    cudaFuncSetAttribute(gemm_mma2, cudaFuncAttributeMaxDynamicSharedMemorySize, GSMEM_B);
    dim3 gq(DIM_ / 128, (B_ * T_) / 128);       // (16,32)
    dim3 gkv(2 * KD_ / 128, (B_ * T_) / 128);   // (8,32) K+V fused
    gemm_mma <<<gq,  256, GSMEM_B>>>(x, Wq, q, B_ * T_, DIM_, DIM_);
    gemm_mma2<<<gkv, 256, GSMEM_B>>>(x, Wk, kk, Wv, vv, B_ * T_, KD_, DIM_);

    // 3) RMSNorm + RoPE (+gain for q) -> bf16 hi/lo ; V split
    norm_rope_kernel<<<(B_ * T_ * NH_  * 32) / 256, 256>>>(q,  qg,      NH_,  qh, ql);
    norm_rope_kernel<<<(B_ * T_ * NKV_ * 32) / 256, 256>>>(kk, nullptr, NKV_, kh, kl);
    split_kernel<<<(B_ * T_ * KD_ / 4 + 255) / 256, 256>>>(vv, vh, vl, B_ * T_ * KD_ / 4);

    // 4) causal GQA flash attention (cp.async double-buffered, heavy tiles first)
    cudaFuncSetAttribute(flash_mma, cudaFuncAttributeMaxDynamicSharedMemorySize, FSMEM);
    flash_mma<<<dim3(T_ / 128, NH_, B_), 256, FSMEM>>>(qh, ql, kh, kl, vh, vl, y);

    // 5) output projection
    gemm_mma<<<gq, 256, GSMEM_B>>>(y, Wp, out, B_ * T_, DIM_, DIM_);
}

// round 5
// speedup vs baseline: 3.0748x; 1.1857x over previous
#include <cuda_runtime.h>
#include <cuda_bf16.h>
#include <cuda_fp16.h>
#include <math.h>
#include <stdint.h>

#define B_    2
#define T_    2048
#define DIM_  2048
#define NH_   16
#define NKV_  4
#define HD_   128
#define KD_   512
#define GQ_   (NH_ / NKV_)
#define EPS_  1.1920928955078125e-07f

// ---------------- scratch ----------------------------------------------------
__device__ float g_q[(size_t)B_ * T_ * DIM_];   // fp32 q (pre-norm)
__device__ float g_k[(size_t)B_ * T_ * KD_];    // fp32 k (pre-norm)
__device__ float g_v[(size_t)B_ * T_ * KD_];    // fp32 v
__device__ float g_y[(size_t)B_ * T_ * DIM_];   // attention output
__device__ float g_cos[T_ * (HD_ / 2)];
__device__ float g_sin[T_ * (HD_ / 2)];
// fp16 post-norm/rope buffers for flash (scale*L2E*gain folded into q)
__device__ __half g_qH[(size_t)B_ * T_ * DIM_];
__device__ __half g_kH[(size_t)B_ * T_ * KD_];
__device__ __half g_vH[(size_t)B_ * T_ * KD_];

// ---------------- helpers ----------------------------------------------------
__device__ __forceinline__ uint32_t smem_u32(const void* p) {
    uint32_t a;
    asm("{ .reg .u64 t; cvta.to.shared.u64 t, %1; cvt.u32.u64 %0, t; }"
        : "=r"(a) : "l"(p));
    return a;
}
__device__ __forceinline__ void mma_bf16(float* d, const uint32_t* a, const uint32_t* b) {
    asm volatile("mma.sync.aligned.m16n8k16.row.col.f32.bf16.bf16.f32 "
        "{%0,%1,%2,%3}, {%4,%5,%6,%7}, {%8,%9}, {%0,%1,%2,%3};"
        : "+f"(d[0]), "+f"(d[1]), "+f"(d[2]), "+f"(d[3])
        : "r"(a[0]), "r"(a[1]), "r"(a[2]), "r"(a[3]), "r"(b[0]), "r"(b[1]));
}
__device__ __forceinline__ void mma_f16(float* d, const uint32_t* a, const uint32_t* b) {
    asm volatile("mma.sync.aligned.m16n8k16.row.col.f32.f16.f16.f32 "
        "{%0,%1,%2,%3}, {%4,%5,%6,%7}, {%8,%9}, {%0,%1,%2,%3};"
        : "+f"(d[0]), "+f"(d[1]), "+f"(d[2]), "+f"(d[3])
        : "r"(a[0]), "r"(a[1]), "r"(a[2]), "r"(a[3]), "r"(b[0]), "r"(b[1]));
}
__device__ __forceinline__ void ldsm_x4(uint32_t* r, uint32_t addr) {
    asm volatile("ldmatrix.sync.aligned.m8n8.x4.shared.b16 {%0,%1,%2,%3}, [%4];"
        : "=r"(r[0]), "=r"(r[1]), "=r"(r[2]), "=r"(r[3]) : "r"(addr));
}
__device__ __forceinline__ void ldsm_x2(uint32_t* r, uint32_t addr) {
    asm volatile("ldmatrix.sync.aligned.m8n8.x2.shared.b16 {%0,%1}, [%2];"
        : "=r"(r[0]), "=r"(r[1]) : "r"(addr));
}
__device__ __forceinline__ void ldsm_x4_t(uint32_t* r, uint32_t addr) {
    asm volatile("ldmatrix.sync.aligned.m8n8.x4.trans.shared.b16 {%0,%1,%2,%3}, [%4];"
        : "=r"(r[0]), "=r"(r[1]), "=r"(r[2]), "=r"(r[3]) : "r"(addr));
}
__device__ __forceinline__ void cp16(uint32_t dst, const void* src) {
    asm volatile("cp.async.cg.shared.global [%0], [%1], 16;" :: "r"(dst), "l"(src));
}
#define CP_COMMIT() asm volatile("cp.async.commit_group;" ::: "memory")
#define CP_WAIT0()  asm volatile("cp.async.wait_group 0;" ::: "memory")

// split float4 -> hi bf16x2 pair + lo bf16x2 pair (GEMM path)
__device__ __forceinline__ void split4(float4 f, uint2& hi, uint2& lo) {
    __nv_bfloat162 h0 = __floats2bfloat162_rn(f.x, f.y);
    __nv_bfloat162 h1 = __floats2bfloat162_rn(f.z, f.w);
    float2 g0 = __bfloat1622float2(h0), g1 = __bfloat1622float2(h1);
    __nv_bfloat162 l0 = __floats2bfloat162_rn(f.x - g0.x, f.y - g0.y);
    __nv_bfloat162 l1 = __floats2bfloat162_rn(f.z - g1.x, f.w - g1.y);
    hi.x = *(uint32_t*)&h0; hi.y = *(uint32_t*)&h1;
    lo.x = *(uint32_t*)&l0; lo.y = *(uint32_t*)&l1;
}
#define NEG_INF __int_as_float(0xff800000)

// ---------------- RoPE tables ------------------------------------------------
__global__ void rope_table_kernel() {
    int idx = blockIdx.x * blockDim.x + threadIdx.x;
    if (idx >= T_ * (HD_ / 2)) return;
    int t = idx >> 6;
    int i = idx & 63;
    double base = 10000.0;
    if (T_ > 1024)
        base = 10000.0 * pow((double)T_ / 1024.0, (double)HD_ / (double)(HD_ - 2));
    double f = pow(base, -((double)(2 * i)) / (double)HD_);
    double a = (double)t * f;
    g_cos[idx] = (float)cos(a);
    g_sin[idx] = (float)sin(a);
}

// ---------------- RMSNorm + RoPE (+gain) -> fp16 ------------------------------
// post_mul: extra factor folded in (q: scale*log2e, k/v: 1)
__global__ void norm_rope_kernel(const float* __restrict__ data,
                                 const float* __restrict__ gain, int nheads,
                                 float post_mul, __half* __restrict__ oh)
{
    int gw   = (blockIdx.x * blockDim.x + threadIdx.x) >> 5;
    int lane = threadIdx.x & 31;
    int h = gw % nheads;
    int t = (gw / nheads) % T_;

    float4 v = *(const float4*)(data + (size_t)gw * HD_ + lane * 4);
    float ss = v.x * v.x + v.y * v.y + v.z * v.z + v.w * v.w;
    #pragma unroll
    for (int off = 16; off; off >>= 1)
        ss += __shfl_xor_sync(0xffffffffu, ss, off);
    float r = rsqrtf(ss * (1.f / HD_) + EPS_);

    float x[4] = { v.x * r, v.y * r, v.z * r, v.w * r };
    bool hi = lane >= 16;
    float g = (gain ? gain[h] : 1.f) * post_mul;

    float out[4];
    #pragma unroll
    for (int j = 0; j < 4; ++j) {
        float p = __shfl_xor_sync(0xffffffffu, x[j], 16);
        int i   = (lane & 15) * 4 + j;
        float c = g_cos[t * 64 + i];
        float s = g_sin[t * 64 + i];
        out[j] = (hi ? (x[j] * c - p * s) : (x[j] * c + p * s)) * g;
    }
    __half2 h0 = __floats2half2_rn(out[0], out[1]);
    __half2 h1 = __floats2half2_rn(out[2], out[3]);
    uint2 pk = make_uint2(*(uint32_t*)&h0, *(uint32_t*)&h1);
    *(uint2*)(oh + (size_t)gw * HD_ + lane * 4) = pk;
}

// ---------------- fp32 -> fp16 (for V) ----------------------------------------
__global__ void tohalf_kernel(const float* __restrict__ src,
                              __half* __restrict__ dst, int n4) {
    int i = blockIdx.x * blockDim.x + threadIdx.x;
    if (i >= n4) return;
    float4 f = ((const float4*)src)[i];
    __half2 h0 = __floats2half2_rn(f.x, f.y);
    __half2 h1 = __floats2half2_rn(f.z, f.w);
    ((uint2*)dst)[i] = make_uint2(*(uint32_t*)&h0, *(uint32_t*)&h1);
}

// ---------------- mma.sync GEMM body (3-term bf16, unchanged) -----------------
#define GA_STRIDE 144
#define GTILE_B   (128 * GA_STRIDE)
#define GSTAGE_B  (4 * GTILE_B)
#define GSMEM_B   (2 * GSTAGE_B)

__device__ __forceinline__ void gemm_body(
    const float* __restrict__ A, const float* __restrict__ Bm,
    float* __restrict__ C, int M, int N, int K, int bm, int bn)
{
    extern __shared__ char sm[];
    const uint32_t sb = smem_u32(sm);
    const int tid = threadIdx.x, wid = tid >> 5, lane = tid & 31;
    const int wm = wid & 1, wn = wid >> 1;

    float acc[4][4][4];
    #pragma unroll
    for (int i = 0; i < 4; ++i)
        #pragma unroll
        for (int j = 0; j < 4; ++j)
            #pragma unroll
            for (int q = 0; q < 4; ++q) acc[i][j][q] = 0.f;

    const int niter = K / 64;

    auto load_stage = [&](int it, int buf) {
        const int k0 = it * 64;
        char* s = sm + buf * GSTAGE_B;
        #pragma unroll
        for (int p = 0; p < 16; ++p) {
            int idx  = tid + p * 256;
            int tile = idx >> 11;
            int r    = (idx >> 4) & 127;
            int c4   = idx & 15;
            const float* src = tile ? Bm : A;
            int rowg = (tile ? bn : bm) + r;
            float4 f = *(const float4*)(src + (size_t)rowg * K + k0 + c4 * 4);
            uint2 hi, lo; split4(f, hi, lo);
            char* dh = s + (tile * 2) * GTILE_B + r * GA_STRIDE + c4 * 8;
            *(uint2*)dh = hi;
            *(uint2*)(dh + GTILE_B) = lo;
        }
    };

    load_stage(0, 0);
    __syncthreads();

    for (int it = 0; it < niter; ++it) {
        const int buf = it & 1;
        const uint32_t sbuf = sb + buf * GSTAGE_B;
        #pragma unroll
        for (int ks = 0; ks < 4; ++ks) {
            uint32_t ah[4][4], al[4][4], bh[4][2], bl[4][2];
            #pragma unroll
            for (int mt = 0; mt < 4; ++mt) {
                uint32_t ra = sbuf + (wm * 64 + mt * 16 + (lane & 15)) * GA_STRIDE
                            + ks * 32 + ((lane >> 4) << 4);
                ldsm_x4(ah[mt], ra);
                ldsm_x4(al[mt], ra + GTILE_B);
            }
            #pragma unroll
            for (int nt = 0; nt < 4; ++nt) {
                uint32_t rb = sbuf + 2 * GTILE_B
                            + (wn * 32 + nt * 8 + (lane & 7)) * GA_STRIDE
                            + ks * 32 + ((lane & 8) << 1);
                ldsm_x2(bh[nt], rb);
                ldsm_x2(bl[nt], rb + GTILE_B);
            }
            #pragma unroll
            for (int mt = 0; mt < 4; ++mt)
                #pragma unroll
                for (int nt = 0; nt < 4; ++nt) {
                    mma_bf16(acc[mt][nt], ah[mt], bh[nt]);
                    mma_bf16(acc[mt][nt], ah[mt], bl[nt]);
                    mma_bf16(acc[mt][nt], al[mt], bh[nt]);
                }
        }
        if (it + 1 < niter) load_stage(it + 1, buf ^ 1);
        __syncthreads();
    }

    #pragma unroll
    for (int mt = 0; mt < 4; ++mt)
        #pragma unroll
        for (int nt = 0; nt < 4; ++nt) {
            int row = bm + wm * 64 + mt * 16 + (lane >> 2);
            int col = bn + wn * 32 + nt * 8 + 2 * (lane & 3);
            *(float2*)(C + (size_t)row * N + col) =
                make_float2(acc[mt][nt][0], acc[mt][nt][1]);
            *(float2*)(C + (size_t)(row + 8) * N + col) =
                make_float2(acc[mt][nt][2], acc[mt][nt][3]);
        }
}

__global__ void __launch_bounds__(256, 1) gemm_mma(
    const float* __restrict__ A, const float* __restrict__ B,
    float* __restrict__ C, int M, int N, int K)
{
    gemm_body(A, B, C, M, N, K, blockIdx.y * 128, blockIdx.x * 128);
}

__global__ void __launch_bounds__(256, 1) gemm_mma2(
    const float* __restrict__ A,
    const float* __restrict__ B1, float* __restrict__ C1,
    const float* __restrict__ B2, float* __restrict__ C2,
    int M, int N, int K)
{
    int half = gridDim.x >> 1;
    if (blockIdx.x < half)
        gemm_body(A, B1, C1, M, N, K, blockIdx.y * 128, blockIdx.x * 128);
    else
        gemm_body(A, B2, C2, M, N, K, blockIdx.y * 128, (blockIdx.x - half) * 128);
}

// ---------------- flash attention: 1-term fp16, Q in registers ----------------
// Q tile 128 rows, KV tile 64 keys, 8 warps (warp owns 16 Q rows).
// smem: Q (128x272B) | stage0 {K,V} | stage1 {K,V}; stage part = 64x272B.
#define FST    272
#define QT     (128 * FST)            // 34816
#define KVP    (64 * FST)             // 17408 per tensor
#define STG    (2 * KVP)              // K|V = 34816
#define FSMEM  (QT + 2 * STG)         // 104448

__global__ void __launch_bounds__(256, 1) flash_mma(
    const __half* __restrict__ qH, const __half* __restrict__ kH,
    const __half* __restrict__ vH, float* __restrict__ y)
{
    extern __shared__ char sm[];
    const uint32_t sb = smem_u32(sm);
    const int tid = threadIdx.x, wid = tid >> 5, lane = tid & 31;
    const int itq = (gridDim.x - 1) - blockIdx.x;   // heavy tiles first
    const int h = blockIdx.y, b = blockIdx.z;
    const int kvh = h / GQ_;
    const int t0q = itq * 128;
    const int jmax = 2 * itq + 1;

    // --- async load Q tile (fp16, 128 x 256B) ---
    #pragma unroll
    for (int p = 0; p < 8; ++p) {
        int idx = tid + p * 256;
        int r = (idx >> 4) & 127, c = idx & 15;
        cp16(sb + r * FST + c * 16,
             qH + ((size_t)(b * T_ + t0q + r) * NH_ + h) * HD_ + c * 8);
    }
    // --- async load KV stage 0 ---
    #pragma unroll
    for (int p = 0; p < 8; ++p) {
        int idx = tid + p * 256;
        int part = idx >> 10;                // 0=K,1=V
        int r = (idx >> 4) & 63, c = idx & 15;
        const __half* src = part ? vH : kH;
        cp16(sb + QT + part * KVP + r * FST + c * 16,
             src + ((size_t)(b * T_ + r) * NKV_ + kvh) * HD_ + c * 8);
    }
    CP_COMMIT();
    CP_WAIT0();
    __syncthreads();

    // --- Q fragments into registers (held across all KV tiles) ---
    uint32_t QF[8][4];
    #pragma unroll
    for (int ks = 0; ks < 8; ++ks) {
        uint32_t ra = sb + (wid * 16 + (lane & 15)) * FST
                    + ks * 32 + ((lane >> 4) << 4);
        ldsm_x4(QF[ks], ra);
    }

    float m0 = NEG_INF, m1 = NEG_INF, l0 = 0.f, l1 = 0.f;
    float O[16][4];
    #pragma unroll
    for (int nt = 0; nt < 16; ++nt)
        #pragma unroll
        for (int j = 0; j < 4; ++j) O[nt][j] = 0.f;

    const int row_a = t0q + wid * 16 + (lane >> 2);

    for (int jt = 0; jt <= jmax; ++jt) {
        const int buf = jt & 1;
        if (jt > 0) { CP_WAIT0(); __syncthreads(); }
        // prefetch next stage (overlaps compute)
        if (jt + 1 <= jmax) {
            const int t0n = (jt + 1) * 64;
            #pragma unroll
            for (int p = 0; p < 8; ++p) {
                int idx = tid + p * 256;
                int part = idx >> 10;
                int r = (idx >> 4) & 63, c = idx & 15;
                const __half* src = part ? vH : kH;
                cp16(sb + QT + (buf ^ 1) * STG + part * KVP + r * FST + c * 16,
                     src + ((size_t)(b * T_ + t0n + r) * NKV_ + kvh) * HD_ + c * 8);
            }
            CP_COMMIT();
        }

        const uint32_t base_k = sb + QT + buf * STG;
        const int t0k = jt * 64;

        // ---- S = Q K^T (1-term fp16; scale*log2e pre-folded into Q) ----
        float S[8][4];
        #pragma unroll
        for (int nt = 0; nt < 8; ++nt)
            #pragma unroll
            for (int j = 0; j < 4; ++j) S[nt][j] = 0.f;

        #pragma unroll
        for (int ks = 0; ks < 8; ++ks) {
            #pragma unroll
            for (int ntp = 0; ntp < 4; ++ntp) {
                uint32_t bh[4];
                uint32_t rb = base_k
                            + (ntp * 16 + (lane & 7) + ((lane >> 4) << 3)) * FST
                            + ks * 32 + (((lane >> 3) & 1) << 4);
                ldsm_x4(bh, rb);
                mma_f16(S[2 * ntp],     QF[ks], bh);
                mma_f16(S[2 * ntp + 1], QF[ks], bh + 2);
            }
        }

        // ---- causal mask + online softmax (log2 domain) ----
        const bool diag = (jt >= 2 * itq);
        float ml0 = NEG_INF, ml1 = NEG_INF;
        #pragma unroll
        for (int nt = 0; nt < 8; ++nt) {
            int c = t0k + nt * 8 + 2 * (lane & 3);
            if (diag) {
                if (c     > row_a)     S[nt][0] = NEG_INF;
                if (c + 1 > row_a)     S[nt][1] = NEG_INF;
                if (c     > row_a + 8) S[nt][2] = NEG_INF;
                if (c + 1 > row_a + 8) S[nt][3] = NEG_INF;
            }
            ml0 = fmaxf(ml0, fmaxf(S[nt][0], S[nt][1]));
            ml1 = fmaxf(ml1, fmaxf(S[nt][2], S[nt][3]));
        }
        ml0 = fmaxf(ml0, __shfl_xor_sync(0xffffffffu, ml0, 1));
        ml0 = fmaxf(ml0, __shfl_xor_sync(0xffffffffu, ml0, 2));
        ml1 = fmaxf(ml1, __shfl_xor_sync(0xffffffffu, ml1, 1));
        ml1 = fmaxf(ml1, __shfl_xor_sync(0xffffffffu, ml1, 2));

        float mn0 = fmaxf(m0, ml0), mn1 = fmaxf(m1, ml1);
        float es0 = exp2f(m0 - mn0);
        float es1 = exp2f(m1 - mn1);
        m0 = mn0; m1 = mn1;

        float sum0 = 0.f, sum1 = 0.f;
        uint32_t PH[16];
        #pragma unroll
        for (int nt = 0; nt < 8; ++nt) {
            float p0 = exp2f(S[nt][0] - mn0);
            float p1 = exp2f(S[nt][1] - mn0);
            float p2 = exp2f(S[nt][2] - mn1);
            float p3 = exp2f(S[nt][3] - mn1);
            sum0 += p0 + p1;  sum1 += p2 + p3;
            __half2 hA = __floats2half2_rn(p0, p1);
            __half2 hB = __floats2half2_rn(p2, p3);
            PH[2 * nt]     = *(uint32_t*)&hA;
            PH[2 * nt + 1] = *(uint32_t*)&hB;
        }
        sum0 += __shfl_xor_sync(0xffffffffu, sum0, 1);
        sum0 += __shfl_xor_sync(0xffffffffu, sum0, 2);
        sum1 += __shfl_xor_sync(0xffffffffu, sum1, 1);
        sum1 += __shfl_xor_sync(0xffffffffu, sum1, 2);
        l0 = l0 * es0 + sum0;
        l1 = l1 * es1 + sum1;
        #pragma unroll
        for (int nt = 0; nt < 16; ++nt) {
            O[nt][0] *= es0; O[nt][1] *= es0;
            O[nt][2] *= es1; O[nt][3] *= es1;
        }

        // ---- O += P V (1-term fp16) ----
        const uint32_t base_v = base_k + KVP;
        #pragma unroll
        for (int kt = 0; kt < 4; ++kt) {
            uint32_t pa[4] = { PH[4*kt], PH[4*kt+1], PH[4*kt+2], PH[4*kt+3] };
            #pragma unroll
            for (int ntp = 0; ntp < 8; ++ntp) {
                uint32_t bh[4];
                uint32_t rv = base_v
                            + (kt * 16 + (lane & 7) + (lane & 8)) * FST
                            + ntp * 32 + ((lane >> 4) << 4);
                ldsm_x4_t(bh, rv);
                mma_f16(O[2 * ntp],     pa, bh);
                mma_f16(O[2 * ntp + 1], pa, bh + 2);
            }
        }
    }

    // ---- epilogue ----
    float inv0 = 1.f / l0, inv1 = 1.f / l1;
    #pragma unroll
    for (int nt = 0; nt < 16; ++nt) {
        int c = nt * 8 + 2 * (lane & 3);
        size_t baseA = ((size_t)(b * T_ + row_a) * NH_ + h) * HD_ + c;
        size_t baseB = ((size_t)(b * T_ + row_a + 8) * NH_ + h) * HD_ + c;
        *(float2*)(y + baseA) = make_float2(O[nt][0] * inv0, O[nt][1] * inv0);
        *(float2*)(y + baseB) = make_float2(O[nt][2] * inv1, O[nt][3] * inv1);
    }
}

// ---------------------------------------------------------------------------
extern "C" void kernel_launch(void* const* d_in, const int* in_sizes, int n_in,
                              void* d_out, int out_size)
{
    const float* x  = (const float*)d_in[0];
    const float* Wq = (const float*)d_in[1];
    const float* Wk = (const float*)d_in[2];
    const float* Wv = (const float*)d_in[3];
    const float* Wp = (const float*)d_in[4];
    const float* qg = (const float*)d_in[5];
    float* out = (float*)d_out;

    float *q, *kk, *vv, *y;
    cudaGetSymbolAddress((void**)&q,  g_q);
    cudaGetSymbolAddress((void**)&kk, g_k);
    cudaGetSymbolAddress((void**)&vv, g_v);
    cudaGetSymbolAddress((void**)&y,  g_y);
    __half *qh, *kh, *vh;
    cudaGetSymbolAddress((void**)&qh, g_qH);
    cudaGetSymbolAddress((void**)&kh, g_kH);
    cudaGetSymbolAddress((void**)&vh, g_vH);

    // 1) RoPE tables
    rope_table_kernel<<<(T_ * 64 + 255) / 256, 256>>>();

    // 2) projections (3-term bf16 mma.sync)
    cudaFuncSetAttribute(gemm_mma,  cudaFuncAttributeMaxDynamicSharedMemorySize, GSMEM_B);
    cudaFuncSetAttribute(gemm_mma2, cudaFuncAttributeMaxDynamicSharedMemorySize, GSMEM_B);
    dim3 gq(DIM_ / 128, (B_ * T_) / 128);
    dim3 gkv(2 * KD_ / 128, (B_ * T_) / 128);
    gemm_mma <<<gq,  256, GSMEM_B>>>(x, Wq, q, B_ * T_, DIM_, DIM_);
    gemm_mma2<<<gkv, 256, GSMEM_B>>>(x, Wk, kk, Wv, vv, B_ * T_, KD_, DIM_);

    // 3) RMSNorm + RoPE -> fp16 (q gets gain*scale*log2e folded in)
    const float QMUL = 0.08838834764831845f * 1.44269504088896340736f;
    norm_rope_kernel<<<(B_ * T_ * NH_  * 32) / 256, 256>>>(q,  qg,      NH_,  QMUL, qh);
    norm_rope_kernel<<<(B_ * T_ * NKV_ * 32) / 256, 256>>>(kk, nullptr, NKV_, 1.0f, kh);
    tohalf_kernel<<<(B_ * T_ * KD_ / 4 + 255) / 256, 256>>>(vv, vh, B_ * T_ * KD_ / 4);

    // 4) causal GQA flash attention (1-term fp16)
    cudaFuncSetAttribute(flash_mma, cudaFuncAttributeMaxDynamicSharedMemorySize, FSMEM);
    flash_mma<<<dim3(T_ / 128, NH_, B_), 256, FSMEM>>>(qh, kh, vh, y);

    // 5) output projection
    gemm_mma<<<gq, 256, GSMEM_B>>>(y, Wp, out, B_ * T_, DIM_, DIM_);
}

// round 6
// speedup vs baseline: 3.2397x; 1.0536x over previous
#include <cuda_runtime.h>
#include <cuda_bf16.h>
#include <cuda_fp16.h>
#include <math.h>
#include <stdint.h>

#define B_    2
#define T_    2048
#define DIM_  2048
#define NH_   16
#define NKV_  4
#define HD_   128
#define KD_   512
#define GQ_   (NH_ / NKV_)
#define EPS_  1.1920928955078125e-07f

// ---------------- scratch ----------------------------------------------------
__device__ float g_q[(size_t)B_ * T_ * DIM_];   // fp32 q (pre-norm)
__device__ float g_k[(size_t)B_ * T_ * KD_];    // fp32 k (pre-norm)
__device__ float g_cos[T_ * (HD_ / 2)];
__device__ float g_sin[T_ * (HD_ / 2)];
// fp16 flash inputs
__device__ __half g_qH[(size_t)B_ * T_ * DIM_];
__device__ __half g_kH[(size_t)B_ * T_ * KD_];
__device__ __half g_vH[(size_t)B_ * T_ * KD_];
// bf16 hi/lo operands
__device__ __nv_bfloat16 g_xh[(size_t)B_ * T_ * DIM_];
__device__ __nv_bfloat16 g_xl[(size_t)B_ * T_ * DIM_];
__device__ __nv_bfloat16 g_wqh[(size_t)DIM_ * DIM_];
__device__ __nv_bfloat16 g_wql[(size_t)DIM_ * DIM_];
__device__ __nv_bfloat16 g_wkh[(size_t)KD_ * DIM_];
__device__ __nv_bfloat16 g_wkl[(size_t)KD_ * DIM_];
__device__ __nv_bfloat16 g_wvh[(size_t)KD_ * DIM_];
__device__ __nv_bfloat16 g_wvl[(size_t)KD_ * DIM_];
__device__ __nv_bfloat16 g_wph[(size_t)DIM_ * DIM_];
__device__ __nv_bfloat16 g_wpl[(size_t)DIM_ * DIM_];
__device__ __nv_bfloat16 g_yh[(size_t)B_ * T_ * DIM_];   // flash out hi
__device__ __nv_bfloat16 g_yl[(size_t)B_ * T_ * DIM_];   // flash out lo

// ---------------- helpers ----------------------------------------------------
__device__ __forceinline__ uint32_t smem_u32(const void* p) {
    uint32_t a;
    asm("{ .reg .u64 t; cvta.to.shared.u64 t, %1; cvt.u32.u64 %0, t; }"
        : "=r"(a) : "l"(p));
    return a;
}
__device__ __forceinline__ void mma_bf16(float* d, const uint32_t* a, const uint32_t* b) {
    asm volatile("mma.sync.aligned.m16n8k16.row.col.f32.bf16.bf16.f32 "
        "{%0,%1,%2,%3}, {%4,%5,%6,%7}, {%8,%9}, {%0,%1,%2,%3};"
        : "+f"(d[0]), "+f"(d[1]), "+f"(d[2]), "+f"(d[3])
        : "r"(a[0]), "r"(a[1]), "r"(a[2]), "r"(a[3]), "r"(b[0]), "r"(b[1]));
}
__device__ __forceinline__ void mma_f16(float* d, const uint32_t* a, const uint32_t* b) {
    asm volatile("mma.sync.aligned.m16n8k16.row.col.f32.f16.f16.f32 "
        "{%0,%1,%2,%3}, {%4,%5,%6,%7}, {%8,%9}, {%0,%1,%2,%3};"
        : "+f"(d[0]), "+f"(d[1]), "+f"(d[2]), "+f"(d[3])
        : "r"(a[0]), "r"(a[1]), "r"(a[2]), "r"(a[3]), "r"(b[0]), "r"(b[1]));
}
__device__ __forceinline__ void ldsm_x4(uint32_t* r, uint32_t addr) {
    asm volatile("ldmatrix.sync.aligned.m8n8.x4.shared.b16 {%0,%1,%2,%3}, [%4];"
        : "=r"(r[0]), "=r"(r[1]), "=r"(r[2]), "=r"(r[3]) : "r"(addr));
}
__device__ __forceinline__ void ldsm_x4_t(uint32_t* r, uint32_t addr) {
    asm volatile("ldmatrix.sync.aligned.m8n8.x4.trans.shared.b16 {%0,%1,%2,%3}, [%4];"
        : "=r"(r[0]), "=r"(r[1]), "=r"(r[2]), "=r"(r[3]) : "r"(addr));
}
__device__ __forceinline__ void cp16(uint32_t dst, const void* src) {
    asm volatile("cp.async.cg.shared.global [%0], [%1], 16;" :: "r"(dst), "l"(src));
}
#define CP_COMMIT() asm volatile("cp.async.commit_group;" ::: "memory")
#define CP_WAIT0()  asm volatile("cp.async.wait_group 0;" ::: "memory")

__device__ __forceinline__ void split4(float4 f, uint2& hi, uint2& lo) {
    __nv_bfloat162 h0 = __floats2bfloat162_rn(f.x, f.y);
    __nv_bfloat162 h1 = __floats2bfloat162_rn(f.z, f.w);
    float2 g0 = __bfloat1622float2(h0), g1 = __bfloat1622float2(h1);
    __nv_bfloat162 l0 = __floats2bfloat162_rn(f.x - g0.x, f.y - g0.y);
    __nv_bfloat162 l1 = __floats2bfloat162_rn(f.z - g1.x, f.w - g1.y);
    hi.x = *(uint32_t*)&h0; hi.y = *(uint32_t*)&h1;
    lo.x = *(uint32_t*)&l0; lo.y = *(uint32_t*)&l1;
}
#define NEG_INF __int_as_float(0xff800000)

// ---------------- RoPE tables ------------------------------------------------
__global__ void rope_table_kernel() {
    int idx = blockIdx.x * blockDim.x + threadIdx.x;
    if (idx >= T_ * (HD_ / 2)) return;
    int t = idx >> 6;
    int i = idx & 63;
    double base = 10000.0;
    if (T_ > 1024)
        base = 10000.0 * pow((double)T_ / 1024.0, (double)HD_ / (double)(HD_ - 2));
    double f = pow(base, -((double)(2 * i)) / (double)HD_);
    double a = (double)t * f;
    g_cos[idx] = (float)cos(a);
    g_sin[idx] = (float)sin(a);
}

// ---------------- fused hi/lo split of x + all weights ------------------------
#define S_X   (B_ * T_ * DIM_ / 4)       // 2097152
#define S_WQ  (DIM_ * DIM_ / 4)          // 1048576
#define S_WK  (KD_ * DIM_ / 4)           // 262144
#define SPLIT_TOT (S_X + 2 * S_WQ + 2 * S_WK)

__global__ void split_all_kernel(const float* __restrict__ x,
                                 const float* __restrict__ Wq,
                                 const float* __restrict__ Wk,
                                 const float* __restrict__ Wv,
                                 const float* __restrict__ Wp)
{
    int i = blockIdx.x * blockDim.x + threadIdx.x;
    const float* src; __nv_bfloat16 *oh, *ol;
    if (i < S_X)                    { src = x;  oh = g_xh;  ol = g_xl; }
    else if ((i -= S_X)  < S_WQ)    { src = Wq; oh = g_wqh; ol = g_wql; }
    else if ((i -= S_WQ) < S_WK)    { src = Wk; oh = g_wkh; ol = g_wkl; }
    else if ((i -= S_WK) < S_WK)    { src = Wv; oh = g_wvh; ol = g_wvl; }
    else                            { i -= S_WK; src = Wp; oh = g_wph; ol = g_wpl; }
    float4 f = ((const float4*)src)[i];
    uint2 h, l; split4(f, h, l);
    ((uint2*)oh)[i] = h;
    ((uint2*)ol)[i] = l;
}

// ---------------- RMSNorm + RoPE (+gain) -> fp16 ------------------------------
__global__ void norm_rope_kernel(const float* __restrict__ data,
                                 const float* __restrict__ gain, int nheads,
                                 float post_mul, __half* __restrict__ oh)
{
    int gw   = (blockIdx.x * blockDim.x + threadIdx.x) >> 5;
    int lane = threadIdx.x & 31;
    int h = gw % nheads;
    int t = (gw / nheads) % T_;

    float4 v = *(const float4*)(data + (size_t)gw * HD_ + lane * 4);
    float ss = v.x * v.x + v.y * v.y + v.z * v.z + v.w * v.w;
    #pragma unroll
    for (int off = 16; off; off >>= 1)
        ss += __shfl_xor_sync(0xffffffffu, ss, off);
    float r = rsqrtf(ss * (1.f / HD_) + EPS_);

    float x[4] = { v.x * r, v.y * r, v.z * r, v.w * r };
    bool hi = lane >= 16;
    float g = (gain ? gain[h] : 1.f) * post_mul;

    float out[4];
    #pragma unroll
    for (int j = 0; j < 4; ++j) {
        float p = __shfl_xor_sync(0xffffffffu, x[j], 16);
        int i   = (lane & 15) * 4 + j;
        float c = g_cos[t * 64 + i];
        float s = g_sin[t * 64 + i];
        out[j] = (hi ? (x[j] * c - p * s) : (x[j] * c + p * s)) * g;
    }
    __half2 h0 = __floats2half2_rn(out[0], out[1]);
    __half2 h1 = __floats2half2_rn(out[2], out[3]);
    *(uint2*)(oh + (size_t)gw * HD_ + lane * 4) =
        make_uint2(*(uint32_t*)&h0, *(uint32_t*)&h1);
}

// ---------------- tensor GEMM: C[M,N]=A[M,K]*B[N,K]^T, bf16 hi/lo, cp.async ----
// 128x128 tile, BK=64, 512 threads (16 warps, 4m x 4n), 32x32 warp tile.
#define GST    144
#define GPART  (128 * GST)     // 18432
#define GSTAGE (4 * GPART)     // 73728 : Ah|Al|Bh|Bl
#define GSMEM  (2 * GSTAGE)    // 147456

__device__ __forceinline__ void gemm_hl_body(
    const __nv_bfloat16* __restrict__ Ah, const __nv_bfloat16* __restrict__ Al,
    const __nv_bfloat16* __restrict__ Bh, const __nv_bfloat16* __restrict__ Bl,
    float* __restrict__ C, __half* __restrict__ Ch,
    int N, int K, int bm, int bn)
{
    extern __shared__ char sm[];
    const uint32_t sb = smem_u32(sm);
    const int tid = threadIdx.x, wid = tid >> 5, lane = tid & 31;
    const int wm = wid & 3, wn = wid >> 2;

    float acc[2][4][4];
    #pragma unroll
    for (int i = 0; i < 2; ++i)
        #pragma unroll
        for (int j = 0; j < 4; ++j)
            #pragma unroll
            for (int q = 0; q < 4; ++q) acc[i][j][q] = 0.f;

    const int niter = K / 64;

    auto load_stage = [&](int it, int buf) {
        const int k0 = it * 64;
        const uint32_t s = sb + buf * GSTAGE;
        #pragma unroll
        for (int p = 0; p < 8; ++p) {
            int idx  = tid + p * 512;
            int part = idx >> 10;              // 0=Ah 1=Al 2=Bh 3=Bl
            int r    = (idx >> 3) & 127;
            int c    = idx & 7;
            const __nv_bfloat16* src = (part == 0) ? Ah : (part == 1) ? Al
                                      : (part == 2) ? Bh : Bl;
            int rowg = (part < 2 ? bm : bn) + r;
            cp16(s + part * GPART + r * GST + c * 16,
                 src + (size_t)rowg * K + k0 + c * 8);
        }
    };

    load_stage(0, 0);
    CP_COMMIT();

    for (int it = 0; it < niter; ++it) {
        const int buf = it & 1;
        CP_WAIT0();
        __syncthreads();
        if (it + 1 < niter) { load_stage(it + 1, buf ^ 1); CP_COMMIT(); }

        const uint32_t sbuf = sb + buf * GSTAGE;
        #pragma unroll
        for (int ks = 0; ks < 4; ++ks) {
            uint32_t ah[2][4], al[2][4], bh[2][4], bl[2][4];
            #pragma unroll
            for (int mt = 0; mt < 2; ++mt) {
                uint32_t ra = sbuf + (wm * 32 + mt * 16 + (lane & 15)) * GST
                            + ks * 32 + ((lane >> 4) << 4);
                ldsm_x4(ah[mt], ra);
                ldsm_x4(al[mt], ra + GPART);
            }
            #pragma unroll
            for (int pr = 0; pr < 2; ++pr) {
                uint32_t rb = sbuf + 2 * GPART
                            + (wn * 32 + pr * 16 + (lane & 7) + ((lane >> 4) << 3)) * GST
                            + ks * 32 + (((lane >> 3) & 1) << 4);
                ldsm_x4(bh[pr], rb);
                ldsm_x4(bl[pr], rb + GPART);
            }
            #pragma unroll
            for (int mt = 0; mt < 2; ++mt)
                #pragma unroll
                for (int nt = 0; nt < 4; ++nt) {
                    const uint32_t* bhp = bh[nt >> 1] + (nt & 1) * 2;
                    const uint32_t* blp = bl[nt >> 1] + (nt & 1) * 2;
                    mma_bf16(acc[mt][nt], ah[mt], bhp);
                    mma_bf16(acc[mt][nt], ah[mt], blp);
                    mma_bf16(acc[mt][nt], al[mt], bhp);
                }
        }
        __syncthreads();
    }

    #pragma unroll
    for (int mt = 0; mt < 2; ++mt)
        #pragma unroll
        for (int nt = 0; nt < 4; ++nt) {
            int row = bm + wm * 32 + mt * 16 + (lane >> 2);
            int col = bn + wn * 32 + nt * 8 + 2 * (lane & 3);
            if (Ch) {
                __half2 a = __floats2half2_rn(acc[mt][nt][0], acc[mt][nt][1]);
                __half2 b = __floats2half2_rn(acc[mt][nt][2], acc[mt][nt][3]);
                *(uint32_t*)(Ch + (size_t)row * N + col)       = *(uint32_t*)&a;
                *(uint32_t*)(Ch + (size_t)(row + 8) * N + col) = *(uint32_t*)&b;
            } else {
                *(float2*)(C + (size_t)row * N + col) =
                    make_float2(acc[mt][nt][0], acc[mt][nt][1]);
                *(float2*)(C + (size_t)(row + 8) * N + col) =
                    make_float2(acc[mt][nt][2], acc[mt][nt][3]);
            }
        }
}

__global__ void __launch_bounds__(512, 1) gemm_hl(
    const __nv_bfloat16* Ah, const __nv_bfloat16* Al,
    const __nv_bfloat16* Bh, const __nv_bfloat16* Bl,
    float* C, int N, int K)
{
    gemm_hl_body(Ah, Al, Bh, Bl, C, nullptr, N, K,
                 blockIdx.y * 128, blockIdx.x * 128);
}

// fused K (fp32 out) + V (fp16 out) projections
__global__ void __launch_bounds__(512, 1) gemm_hl_kv(
    const __nv_bfloat16* Ah, const __nv_bfloat16* Al,
    const __nv_bfloat16* B1h, const __nv_bfloat16* B1l, float* C1,
    const __nv_bfloat16* B2h, const __nv_bfloat16* B2l, __half* C2,
    int N, int K)
{
    int half = gridDim.x >> 1;
    if (blockIdx.x < half)
        gemm_hl_body(Ah, Al, B1h, B1l, C1, nullptr, N, K,
                     blockIdx.y * 128, blockIdx.x * 128);
    else
        gemm_hl_body(Ah, Al, B2h, B2l, nullptr, C2, N, K,
                     blockIdx.y * 128, (blockIdx.x - half) * 128);
}

// ---------------- flash attention: 1-term fp16, Q in registers ----------------
#define FST    272
#define QT     (128 * FST)
#define KVP    (64 * FST)
#define STG    (2 * KVP)
#define FSMEM  (QT + 2 * STG)     // 104448

__global__ void __launch_bounds__(256, 1) flash_mma(
    const __half* __restrict__ qH, const __half* __restrict__ kH,
    const __half* __restrict__ vH,
    __nv_bfloat16* __restrict__ yh, __nv_bfloat16* __restrict__ yl)
{
    extern __shared__ char sm[];
    const uint32_t sb = smem_u32(sm);
    const int tid = threadIdx.x, wid = tid >> 5, lane = tid & 31;
    const int itq = (gridDim.x - 1) - blockIdx.x;   // heavy tiles first
    const int h = blockIdx.y, b = blockIdx.z;
    const int kvh = h / GQ_;
    const int t0q = itq * 128;
    const int jmax = 2 * itq + 1;

    #pragma unroll
    for (int p = 0; p < 8; ++p) {
        int idx = tid + p * 256;
        int r = (idx >> 4) & 127, c = idx & 15;
        cp16(sb + r * FST + c * 16,
             qH + ((size_t)(b * T_ + t0q + r) * NH_ + h) * HD_ + c * 8);
    }
    #pragma unroll
    for (int p = 0; p < 8; ++p) {
        int idx = tid + p * 256;
        int part = idx >> 10;
        int r = (idx >> 4) & 63, c = idx & 15;
        const __half* src = part ? vH : kH;
        cp16(sb + QT + part * KVP + r * FST + c * 16,
             src + ((size_t)(b * T_ + r) * NKV_ + kvh) * HD_ + c * 8);
    }
    CP_COMMIT();
    CP_WAIT0();
    __syncthreads();

    uint32_t QF[8][4];
    #pragma unroll
    for (int ks = 0; ks < 8; ++ks) {
        uint32_t ra = sb + (wid * 16 + (lane & 15)) * FST
                    + ks * 32 + ((lane >> 4) << 4);
        ldsm_x4(QF[ks], ra);
    }

    float m0 = NEG_INF, m1 = NEG_INF, l0 = 0.f, l1 = 0.f;
    float O[16][4];
    #pragma unroll
    for (int nt = 0; nt < 16; ++nt)
        #pragma unroll
        for (int j = 0; j < 4; ++j) O[nt][j] = 0.f;

    const int row_a = t0q + wid * 16 + (lane >> 2);

    for (int jt = 0; jt <= jmax; ++jt) {
        const int buf = jt & 1;
        if (jt > 0) { CP_WAIT0(); __syncthreads(); }
        if (jt + 1 <= jmax) {
            const int t0n = (jt + 1) * 64;
            #pragma unroll
            for (int p = 0; p < 8; ++p) {
                int idx = tid + p * 256;
                int part = idx >> 10;
                int r = (idx >> 4) & 63, c = idx & 15;
                const __half* src = part ? vH : kH;
                cp16(sb + QT + (buf ^ 1) * STG + part * KVP + r * FST + c * 16,
                     src + ((size_t)(b * T_ + t0n + r) * NKV_ + kvh) * HD_ + c * 8);
            }
            CP_COMMIT();
        }

        const uint32_t base_k = sb + QT + buf * STG;
        const int t0k = jt * 64;

        float S[8][4];
        #pragma unroll
        for (int nt = 0; nt < 8; ++nt)
            #pragma unroll
            for (int j = 0; j < 4; ++j) S[nt][j] = 0.f;

        #pragma unroll
        for (int ks = 0; ks < 8; ++ks) {
            #pragma unroll
            for (int ntp = 0; ntp < 4; ++ntp) {
                uint32_t bh[4];
                uint32_t rb = base_k
                            + (ntp * 16 + (lane & 7) + ((lane >> 4) << 3)) * FST
                            + ks * 32 + (((lane >> 3) & 1) << 4);
                ldsm_x4(bh, rb);
                mma_f16(S[2 * ntp],     QF[ks], bh);
                mma_f16(S[2 * ntp + 1], QF[ks], bh + 2);
            }
        }

        const bool diag = (jt >= 2 * itq);
        float ml0 = NEG_INF, ml1 = NEG_INF;
        #pragma unroll
        for (int nt = 0; nt < 8; ++nt) {
            int c = t0k + nt * 8 + 2 * (lane & 3);
            if (diag) {
                if (c     > row_a)     S[nt][0] = NEG_INF;
                if (c + 1 > row_a)     S[nt][1] = NEG_INF;
                if (c     > row_a + 8) S[nt][2] = NEG_INF;
                if (c + 1 > row_a + 8) S[nt][3] = NEG_INF;
            }
            ml0 = fmaxf(ml0, fmaxf(S[nt][0], S[nt][1]));
            ml1 = fmaxf(ml1, fmaxf(S[nt][2], S[nt][3]));
        }
        ml0 = fmaxf(ml0, __shfl_xor_sync(0xffffffffu, ml0, 1));
        ml0 = fmaxf(ml0, __shfl_xor_sync(0xffffffffu, ml0, 2));
        ml1 = fmaxf(ml1, __shfl_xor_sync(0xffffffffu, ml1, 1));
        ml1 = fmaxf(ml1, __shfl_xor_sync(0xffffffffu, ml1, 2));

        float mn0 = fmaxf(m0, ml0), mn1 = fmaxf(m1, ml1);
        float es0 = exp2f(m0 - mn0);
        float es1 = exp2f(m1 - mn1);
        m0 = mn0; m1 = mn1;

        float sum0 = 0.f, sum1 = 0.f;
        uint32_t PH[16];
        #pragma unroll
        for (int nt = 0; nt < 8; ++nt) {
            float p0 = exp2f(S[nt][0] - mn0);
            float p1 = exp2f(S[nt][1] - mn0);
            float p2 = exp2f(S[nt][2] - mn1);
            float p3 = exp2f(S[nt][3] - mn1);
            sum0 += p0 + p1;  sum1 += p2 + p3;
            __half2 hA = __floats2half2_rn(p0, p1);
            __half2 hB = __floats2half2_rn(p2, p3);
            PH[2 * nt]     = *(uint32_t*)&hA;
            PH[2 * nt + 1] = *(uint32_t*)&hB;
        }
        sum0 += __shfl_xor_sync(0xffffffffu, sum0, 1);
        sum0 += __shfl_xor_sync(0xffffffffu, sum0, 2);
        sum1 += __shfl_xor_sync(0xffffffffu, sum1, 1);
        sum1 += __shfl_xor_sync(0xffffffffu, sum1, 2);
        l0 = l0 * es0 + sum0;
        l1 = l1 * es1 + sum1;
        #pragma unroll
        for (int nt = 0; nt < 16; ++nt) {
            O[nt][0] *= es0; O[nt][1] *= es0;
            O[nt][2] *= es1; O[nt][3] *= es1;
        }

        const uint32_t base_v = base_k + KVP;
        #pragma unroll
        for (int kt = 0; kt < 4; ++kt) {
            uint32_t pa[4] = { PH[4*kt], PH[4*kt+1], PH[4*kt+2], PH[4*kt+3] };
            #pragma unroll
            for (int ntp = 0; ntp < 8; ++ntp) {
                uint32_t bh[4];
                uint32_t rv = base_v
                            + (kt * 16 + (lane & 7) + (lane & 8)) * FST
                            + ntp * 32 + ((lane >> 4) << 4);
                ldsm_x4_t(bh, rv);
                mma_f16(O[2 * ntp],     pa, bh);
                mma_f16(O[2 * ntp + 1], pa, bh + 2);
            }
        }
    }

    // ---- epilogue: normalize + bf16 hi/lo split directly ----
    float inv0 = 1.f / l0, inv1 = 1.f / l1;
    #pragma unroll
    for (int nt = 0; nt < 16; ++nt) {
        int c = nt * 8 + 2 * (lane & 3);
        size_t baseA = ((size_t)(b * T_ + row_a) * NH_ + h) * HD_ + c;
        size_t baseB = ((size_t)(b * T_ + row_a + 8) * NH_ + h) * HD_ + c;
        float a0 = O[nt][0] * inv0, a1 = O[nt][1] * inv0;
        float b0 = O[nt][2] * inv1, b1 = O[nt][3] * inv1;
        __nv_bfloat162 hA = __floats2bfloat162_rn(a0, a1);
        __nv_bfloat162 hB = __floats2bfloat162_rn(b0, b1);
        float2 gA = __bfloat1622float2(hA), gB = __bfloat1622float2(hB);
        __nv_bfloat162 lA = __floats2bfloat162_rn(a0 - gA.x, a1 - gA.y);
        __nv_bfloat162 lB = __floats2bfloat162_rn(b0 - gB.x, b1 - gB.y);
        *(uint32_t*)(yh + baseA) = *(uint32_t*)&hA;
        *(uint32_t*)(yl + baseA) = *(uint32_t*)&lA;
        *(uint32_t*)(yh + baseB) = *(uint32_t*)&hB;
        *(uint32_t*)(yl + baseB) = *(uint32_t*)&lB;
    }
}

// ---------------------------------------------------------------------------
extern "C" void kernel_launch(void* const* d_in, const int* in_sizes, int n_in,
                              void* d_out, int out_size)
{
    const float* x  = (const float*)d_in[0];
    const float* Wq = (const float*)d_in[1];
    const float* Wk = (const float*)d_in[2];
    const float* Wv = (const float*)d_in[3];
    const float* Wp = (const float*)d_in[4];
    const float* qg = (const float*)d_in[5];
    float* out = (float*)d_out;

    float *q, *kk;
    cudaGetSymbolAddress((void**)&q,  g_q);
    cudaGetSymbolAddress((void**)&kk, g_k);
    __half *qh16, *kh16, *vh16;
    cudaGetSymbolAddress((void**)&qh16, g_qH);
    cudaGetSymbolAddress((void**)&kh16, g_kH);
    cudaGetSymbolAddress((void**)&vh16, g_vH);
    __nv_bfloat16 *xh,*xl,*wqh,*wql,*wkh,*wkl,*wvh,*wvl,*wph,*wpl,*yh,*yl;
    cudaGetSymbolAddress((void**)&xh,  g_xh);  cudaGetSymbolAddress((void**)&xl,  g_xl);
    cudaGetSymbolAddress((void**)&wqh, g_wqh); cudaGetSymbolAddress((void**)&wql, g_wql);
    cudaGetSymbolAddress((void**)&wkh, g_wkh); cudaGetSymbolAddress((void**)&wkl, g_wkl);
    cudaGetSymbolAddress((void**)&wvh, g_wvh); cudaGetSymbolAddress((void**)&wvl, g_wvl);
    cudaGetSymbolAddress((void**)&wph, g_wph); cudaGetSymbolAddress((void**)&wpl, g_wpl);
    cudaGetSymbolAddress((void**)&yh,  g_yh);  cudaGetSymbolAddress((void**)&yl,  g_yl);

    // (0) RoPE tables
    rope_table_kernel<<<(T_ * 64 + 255) / 256, 256>>>();
    // (1) fused hi/lo split of x + weights
    split_all_kernel<<<SPLIT_TOT / 256, 256>>>(x, Wq, Wk, Wv, Wp);

    // (2) K+V projections (V -> fp16 directly), (3) Q projection [profiled]
    cudaFuncSetAttribute(gemm_hl,    cudaFuncAttributeMaxDynamicSharedMemorySize, GSMEM);
    cudaFuncSetAttribute(gemm_hl_kv, cudaFuncAttributeMaxDynamicSharedMemorySize, GSMEM);
    dim3 gq(DIM_ / 128, (B_ * T_) / 128);       // (16,32)
    dim3 gkv(2 * KD_ / 128, (B_ * T_) / 128);   // (8,32)
    gemm_hl_kv<<<gkv, 512, GSMEM>>>(xh, xl, wkh, wkl, kk, wvh, wvl, vh16, KD_, DIM_);
    gemm_hl   <<<gq,  512, GSMEM>>>(xh, xl, wqh, wql, q, DIM_, DIM_);

    // (4,5) RMSNorm + RoPE -> fp16 (q folds gain*scale*log2e)
    const float QMUL = 0.08838834764831845f * 1.44269504088896340736f;
    norm_rope_kernel<<<(B_ * T_ * NH_  * 32) / 256, 256>>>(q,  qg,      NH_,  QMUL, qh16);
    norm_rope_kernel<<<(B_ * T_ * NKV_ * 32) / 256, 256>>>(kk, nullptr, NKV_, 1.0f, kh16);

    // (6) causal GQA flash attention -> y bf16 hi/lo
    cudaFuncSetAttribute(flash_mma, cudaFuncAttributeMaxDynamicSharedMemorySize, FSMEM);
    flash_mma<<<dim3(T_ / 128, NH_, B_), 256, FSMEM>>>(qh16, kh16, vh16, yh, yl);

    // (7) output projection
    gemm_hl<<<gq, 512, GSMEM>>>(yh, yl, wph, wpl, out, DIM_, DIM_);
}

// round 7
// speedup vs baseline: 4.2137x; 1.3007x over previous
#include <cuda_runtime.h>
#include <cuda_bf16.h>
#include <cuda_fp16.h>
#include <math.h>
#include <stdint.h>

#define B_    2
#define T_    2048
#define DIM_  2048
#define NH_   16
#define NKV_  4
#define HD_   128
#define KD_   512
#define GQ_   (NH_ / NKV_)
#define EPS_  1.1920928955078125e-07f

// ---------------- scratch ----------------------------------------------------
__device__ float g_q[(size_t)B_ * T_ * DIM_];   // fp32 q (pre-norm)
__device__ float g_k[(size_t)B_ * T_ * KD_];    // fp32 k (pre-norm)
__device__ float g_cos[T_ * (HD_ / 2)];
__device__ float g_sin[T_ * (HD_ / 2)];
// fp16 operands
__device__ __half g_xH[(size_t)B_ * T_ * DIM_];   // x fp16 (V-proj A)
__device__ __half g_wvH[(size_t)KD_ * DIM_];      // Wv fp16
__device__ __half g_wpH[(size_t)DIM_ * DIM_];     // Wp fp16
__device__ __half g_qH[(size_t)B_ * T_ * DIM_];
__device__ __half g_kH[(size_t)B_ * T_ * KD_];
__device__ __half g_vH[(size_t)B_ * T_ * KD_];
__device__ __half g_yH[(size_t)B_ * T_ * DIM_];   // flash out fp16
// bf16 hi/lo operands (Q,K projections)
__device__ __nv_bfloat16 g_xh[(size_t)B_ * T_ * DIM_];
__device__ __nv_bfloat16 g_xl[(size_t)B_ * T_ * DIM_];
__device__ __nv_bfloat16 g_wqh[(size_t)DIM_ * DIM_];
__device__ __nv_bfloat16 g_wql[(size_t)DIM_ * DIM_];
__device__ __nv_bfloat16 g_wkh[(size_t)KD_ * DIM_];
__device__ __nv_bfloat16 g_wkl[(size_t)KD_ * DIM_];

// ---------------- helpers ----------------------------------------------------
__device__ __forceinline__ uint32_t smem_u32(const void* p) {
    uint32_t a;
    asm("{ .reg .u64 t; cvta.to.shared.u64 t, %1; cvt.u32.u64 %0, t; }"
        : "=r"(a) : "l"(p));
    return a;
}
__device__ __forceinline__ void mma_bf16(float* d, const uint32_t* a, const uint32_t* b) {
    asm volatile("mma.sync.aligned.m16n8k16.row.col.f32.bf16.bf16.f32 "
        "{%0,%1,%2,%3}, {%4,%5,%6,%7}, {%8,%9}, {%0,%1,%2,%3};"
        : "+f"(d[0]), "+f"(d[1]), "+f"(d[2]), "+f"(d[3])
        : "r"(a[0]), "r"(a[1]), "r"(a[2]), "r"(a[3]), "r"(b[0]), "r"(b[1]));
}
__device__ __forceinline__ void mma_f16(float* d, const uint32_t* a, const uint32_t* b) {
    asm volatile("mma.sync.aligned.m16n8k16.row.col.f32.f16.f16.f32 "
        "{%0,%1,%2,%3}, {%4,%5,%6,%7}, {%8,%9}, {%0,%1,%2,%3};"
        : "+f"(d[0]), "+f"(d[1]), "+f"(d[2]), "+f"(d[3])
        : "r"(a[0]), "r"(a[1]), "r"(a[2]), "r"(a[3]), "r"(b[0]), "r"(b[1]));
}
__device__ __forceinline__ void ldsm_x4(uint32_t* r, uint32_t addr) {
    asm volatile("ldmatrix.sync.aligned.m8n8.x4.shared.b16 {%0,%1,%2,%3}, [%4];"
        : "=r"(r[0]), "=r"(r[1]), "=r"(r[2]), "=r"(r[3]) : "r"(addr));
}
__device__ __forceinline__ void ldsm_x4_t(uint32_t* r, uint32_t addr) {
    asm volatile("ldmatrix.sync.aligned.m8n8.x4.trans.shared.b16 {%0,%1,%2,%3}, [%4];"
        : "=r"(r[0]), "=r"(r[1]), "=r"(r[2]), "=r"(r[3]) : "r"(addr));
}
__device__ __forceinline__ void cp16(uint32_t dst, const void* src) {
    asm volatile("cp.async.cg.shared.global [%0], [%1], 16;" :: "r"(dst), "l"(src));
}
#define CP_COMMIT() asm volatile("cp.async.commit_group;" ::: "memory")
#define CP_WAIT0()  asm volatile("cp.async.wait_group 0;" ::: "memory")

__device__ __forceinline__ void split4(float4 f, uint2& hi, uint2& lo) {
    __nv_bfloat162 h0 = __floats2bfloat162_rn(f.x, f.y);
    __nv_bfloat162 h1 = __floats2bfloat162_rn(f.z, f.w);
    float2 g0 = __bfloat1622float2(h0), g1 = __bfloat1622float2(h1);
    __nv_bfloat162 l0 = __floats2bfloat162_rn(f.x - g0.x, f.y - g0.y);
    __nv_bfloat162 l1 = __floats2bfloat162_rn(f.z - g1.x, f.w - g1.y);
    hi.x = *(uint32_t*)&h0; hi.y = *(uint32_t*)&h1;
    lo.x = *(uint32_t*)&l0; lo.y = *(uint32_t*)&l1;
}
__device__ __forceinline__ uint2 tohalf4(float4 f) {
    __half2 h0 = __floats2half2_rn(f.x, f.y);
    __half2 h1 = __floats2half2_rn(f.z, f.w);
    return make_uint2(*(uint32_t*)&h0, *(uint32_t*)&h1);
}
#define NEG_INF __int_as_float(0xff800000)

// ---------------- RoPE tables ------------------------------------------------
__global__ void rope_table_kernel() {
    int idx = blockIdx.x * blockDim.x + threadIdx.x;
    if (idx >= T_ * (HD_ / 2)) return;
    int t = idx >> 6;
    int i = idx & 63;
    double base = 10000.0;
    if (T_ > 1024)
        base = 10000.0 * pow((double)T_ / 1024.0, (double)HD_ / (double)(HD_ - 2));
    double f = pow(base, -((double)(2 * i)) / (double)HD_);
    double a = (double)t * f;
    g_cos[idx] = (float)cos(a);
    g_sin[idx] = (float)sin(a);
}

// ---------------- fused operand prep ------------------------------------------
// x -> xh/xl bf16 + x fp16 ; Wq,Wk -> hi/lo bf16 ; Wv,Wp -> fp16
#define S_X   (B_ * T_ * DIM_ / 4)       // 2097152
#define S_WQ  (DIM_ * DIM_ / 4)          // 1048576
#define S_WK  (KD_ * DIM_ / 4)           // 262144
#define SPLIT_TOT (S_X + S_WQ + S_WK + S_WK + S_WQ)

__global__ void split_all_kernel(const float* __restrict__ x,
                                 const float* __restrict__ Wq,
                                 const float* __restrict__ Wk,
                                 const float* __restrict__ Wv,
                                 const float* __restrict__ Wp)
{
    int i = blockIdx.x * blockDim.x + threadIdx.x;
    if (i < S_X) {
        float4 f = ((const float4*)x)[i];
        uint2 h, l; split4(f, h, l);
        ((uint2*)g_xh)[i] = h;
        ((uint2*)g_xl)[i] = l;
        ((uint2*)g_xH)[i] = tohalf4(f);
        return;
    }
    i -= S_X;
    if (i < S_WQ) {
        float4 f = ((const float4*)Wq)[i];
        uint2 h, l; split4(f, h, l);
        ((uint2*)g_wqh)[i] = h;
        ((uint2*)g_wql)[i] = l;
        return;
    }
    i -= S_WQ;
    if (i < S_WK) {
        float4 f = ((const float4*)Wk)[i];
        uint2 h, l; split4(f, h, l);
        ((uint2*)g_wkh)[i] = h;
        ((uint2*)g_wkl)[i] = l;
        return;
    }
    i -= S_WK;
    if (i < S_WK) {
        ((uint2*)g_wvH)[i] = tohalf4(((const float4*)Wv)[i]);
        return;
    }
    i -= S_WK;
    ((uint2*)g_wpH)[i] = tohalf4(((const float4*)Wp)[i]);
}

// ---------------- RMSNorm + RoPE (+gain) -> fp16 ------------------------------
__global__ void norm_rope_kernel(const float* __restrict__ data,
                                 const float* __restrict__ gain, int nheads,
                                 float post_mul, __half* __restrict__ oh)
{
    int gw   = (blockIdx.x * blockDim.x + threadIdx.x) >> 5;
    int lane = threadIdx.x & 31;
    int h = gw % nheads;
    int t = (gw / nheads) % T_;

    float4 v = *(const float4*)(data + (size_t)gw * HD_ + lane * 4);
    float ss = v.x * v.x + v.y * v.y + v.z * v.z + v.w * v.w;
    #pragma unroll
    for (int off = 16; off; off >>= 1)
        ss += __shfl_xor_sync(0xffffffffu, ss, off);
    float r = rsqrtf(ss * (1.f / HD_) + EPS_);

    float x[4] = { v.x * r, v.y * r, v.z * r, v.w * r };
    bool hi = lane >= 16;
    float g = (gain ? gain[h] : 1.f) * post_mul;

    float out[4];
    #pragma unroll
    for (int j = 0; j < 4; ++j) {
        float p = __shfl_xor_sync(0xffffffffu, x[j], 16);
        int i   = (lane & 15) * 4 + j;
        float c = g_cos[t * 64 + i];
        float s = g_sin[t * 64 + i];
        out[j] = (hi ? (x[j] * c - p * s) : (x[j] * c + p * s)) * g;
    }
    __half2 h0 = __floats2half2_rn(out[0], out[1]);
    __half2 h1 = __floats2half2_rn(out[2], out[3]);
    *(uint2*)(oh + (size_t)gw * HD_ + lane * 4) =
        make_uint2(*(uint32_t*)&h0, *(uint32_t*)&h1);
}

// ---------------- 3-term bf16 GEMM (Q,K projections) --------------------------
#define GST    144
#define GPART  (128 * GST)
#define GSTAGE (4 * GPART)
#define GSMEM  (2 * GSTAGE)

__global__ void __launch_bounds__(512, 1) gemm_hl(
    const __nv_bfloat16* __restrict__ Ah, const __nv_bfloat16* __restrict__ Al,
    const __nv_bfloat16* __restrict__ Bh, const __nv_bfloat16* __restrict__ Bl,
    float* __restrict__ C, int N, int K)
{
    extern __shared__ char sm[];
    const uint32_t sb = smem_u32(sm);
    const int tid = threadIdx.x, wid = tid >> 5, lane = tid & 31;
    const int wm = wid & 3, wn = wid >> 2;
    const int bm = blockIdx.y * 128, bn = blockIdx.x * 128;

    float acc[2][4][4];
    #pragma unroll
    for (int i = 0; i < 2; ++i)
        #pragma unroll
        for (int j = 0; j < 4; ++j)
            #pragma unroll
            for (int q = 0; q < 4; ++q) acc[i][j][q] = 0.f;

    const int niter = K / 64;

    auto load_stage = [&](int it, int buf) {
        const int k0 = it * 64;
        const uint32_t s = sb + buf * GSTAGE;
        #pragma unroll
        for (int p = 0; p < 8; ++p) {
            int idx  = tid + p * 512;
            int part = idx >> 10;
            int r    = (idx >> 3) & 127;
            int c    = idx & 7;
            const __nv_bfloat16* src = (part == 0) ? Ah : (part == 1) ? Al
                                      : (part == 2) ? Bh : Bl;
            int rowg = (part < 2 ? bm : bn) + r;
            cp16(s + part * GPART + r * GST + c * 16,
                 src + (size_t)rowg * K + k0 + c * 8);
        }
    };

    load_stage(0, 0);
    CP_COMMIT();

    for (int it = 0; it < niter; ++it) {
        const int buf = it & 1;
        CP_WAIT0();
        __syncthreads();
        if (it + 1 < niter) { load_stage(it + 1, buf ^ 1); CP_COMMIT(); }

        const uint32_t sbuf = sb + buf * GSTAGE;
        #pragma unroll
        for (int ks = 0; ks < 4; ++ks) {
            uint32_t ah[2][4], al[2][4], bh[2][4], bl[2][4];
            #pragma unroll
            for (int mt = 0; mt < 2; ++mt) {
                uint32_t ra = sbuf + (wm * 32 + mt * 16 + (lane & 15)) * GST
                            + ks * 32 + ((lane >> 4) << 4);
                ldsm_x4(ah[mt], ra);
                ldsm_x4(al[mt], ra + GPART);
            }
            #pragma unroll
            for (int pr = 0; pr < 2; ++pr) {
                uint32_t rb = sbuf + 2 * GPART
                            + (wn * 32 + pr * 16 + (lane & 7) + ((lane >> 4) << 3)) * GST
                            + ks * 32 + (((lane >> 3) & 1) << 4);
                ldsm_x4(bh[pr], rb);
                ldsm_x4(bl[pr], rb + GPART);
            }
            #pragma unroll
            for (int mt = 0; mt < 2; ++mt)
                #pragma unroll
                for (int nt = 0; nt < 4; ++nt) {
                    const uint32_t* bhp = bh[nt >> 1] + (nt & 1) * 2;
                    const uint32_t* blp = bl[nt >> 1] + (nt & 1) * 2;
                    mma_bf16(acc[mt][nt], ah[mt], bhp);
                    mma_bf16(acc[mt][nt], ah[mt], blp);
                    mma_bf16(acc[mt][nt], al[mt], bhp);
                }
        }
        __syncthreads();
    }

    #pragma unroll
    for (int mt = 0; mt < 2; ++mt)
        #pragma unroll
        for (int nt = 0; nt < 4; ++nt) {
            int row = bm + wm * 32 + mt * 16 + (lane >> 2);
            int col = bn + wn * 32 + nt * 8 + 2 * (lane & 3);
            *(float2*)(C + (size_t)row * N + col) =
                make_float2(acc[mt][nt][0], acc[mt][nt][1]);
            *(float2*)(C + (size_t)(row + 8) * N + col) =
                make_float2(acc[mt][nt][2], acc[mt][nt][3]);
        }
}

// ---------------- 1-term fp16 GEMM (V, out projections) -----------------------
// 128x128 tile, BK=64, 256 threads (8 warps, 2m x 4n), 64x32 warp tile.
#define HST     144
#define HPART   (128 * HST)      // 18432
#define HSTAGE  (2 * HPART)      // 36864 : A|B
#define HSMEM   (2 * HSTAGE)     // 73728 -> 2 CTAs/SM

__global__ void __launch_bounds__(256, 2) gemm_f16(
    const __half* __restrict__ A, const __half* __restrict__ B,
    float* __restrict__ C, __half* __restrict__ Ch, int N, int K)
{
    extern __shared__ char sm[];
    const uint32_t sb = smem_u32(sm);
    const int tid = threadIdx.x, wid = tid >> 5, lane = tid & 31;
    const int wm = wid & 1, wn = wid >> 1;
    const int bm = blockIdx.y * 128, bn = blockIdx.x * 128;

    float acc[4][4][4];
    #pragma unroll
    for (int i = 0; i < 4; ++i)
        #pragma unroll
        for (int j = 0; j < 4; ++j)
            #pragma unroll
            for (int q = 0; q < 4; ++q) acc[i][j][q] = 0.f;

    const int niter = K / 64;

    auto load_stage = [&](int it, int buf) {
        const int k0 = it * 64;
        const uint32_t s = sb + buf * HSTAGE;
        #pragma unroll
        for (int p = 0; p < 8; ++p) {
            int idx  = tid + p * 256;
            int part = idx >> 10;              // 0=A 1=B
            int r    = (idx >> 3) & 127;
            int c    = idx & 7;
            const __half* src = part ? B : A;
            int rowg = (part ? bn : bm) + r;
            cp16(s + part * HPART + r * HST + c * 16,
                 src + (size_t)rowg * K + k0 + c * 8);
        }
    };

    load_stage(0, 0);
    CP_COMMIT();

    for (int it = 0; it < niter; ++it) {
        const int buf = it & 1;
        CP_WAIT0();
        __syncthreads();
        if (it + 1 < niter) { load_stage(it + 1, buf ^ 1); CP_COMMIT(); }

        const uint32_t sbuf = sb + buf * HSTAGE;
        #pragma unroll
        for (int ks = 0; ks < 4; ++ks) {
            uint32_t a[4][4], b[2][4];
            #pragma unroll
            for (int mt = 0; mt < 4; ++mt) {
                uint32_t ra = sbuf + (wm * 64 + mt * 16 + (lane & 15)) * HST
                            + ks * 32 + ((lane >> 4) << 4);
                ldsm_x4(a[mt], ra);
            }
            #pragma unroll
            for (int pr = 0; pr < 2; ++pr) {
                uint32_t rb = sbuf + HPART
                            + (wn * 32 + pr * 16 + (lane & 7) + ((lane >> 4) << 3)) * HST
                            + ks * 32 + (((lane >> 3) & 1) << 4);
                ldsm_x4(b[pr], rb);
            }
            #pragma unroll
            for (int mt = 0; mt < 4; ++mt)
                #pragma unroll
                for (int nt = 0; nt < 4; ++nt)
                    mma_f16(acc[mt][nt], a[mt], b[nt >> 1] + (nt & 1) * 2);
        }
        __syncthreads();
    }

    #pragma unroll
    for (int mt = 0; mt < 4; ++mt)
        #pragma unroll
        for (int nt = 0; nt < 4; ++nt) {
            int row = bm + wm * 64 + mt * 16 + (lane >> 2);
            int col = bn + wn * 32 + nt * 8 + 2 * (lane & 3);
            if (Ch) {
                __half2 u0 = __floats2half2_rn(acc[mt][nt][0], acc[mt][nt][1]);
                __half2 u1 = __floats2half2_rn(acc[mt][nt][2], acc[mt][nt][3]);
                *(uint32_t*)(Ch + (size_t)row * N + col)       = *(uint32_t*)&u0;
                *(uint32_t*)(Ch + (size_t)(row + 8) * N + col) = *(uint32_t*)&u1;
            } else {
                *(float2*)(C + (size_t)row * N + col) =
                    make_float2(acc[mt][nt][0], acc[mt][nt][1]);
                *(float2*)(C + (size_t)(row + 8) * N + col) =
                    make_float2(acc[mt][nt][2], acc[mt][nt][3]);
            }
        }
}

// ---------------- flash attention: 1-term fp16, Q in registers ----------------
#define FST    272
#define QT     (128 * FST)
#define KVP    (64 * FST)
#define STG    (2 * KVP)
#define FSMEM  (QT + 2 * STG)     // 104448

__global__ void __launch_bounds__(256, 1) flash_mma(
    const __half* __restrict__ qH, const __half* __restrict__ kH,
    const __half* __restrict__ vH, __half* __restrict__ y)
{
    extern __shared__ char sm[];
    const uint32_t sb = smem_u32(sm);
    const int tid = threadIdx.x, wid = tid >> 5, lane = tid & 31;
    const int itq = (gridDim.x - 1) - blockIdx.x;
    const int h = blockIdx.y, b = blockIdx.z;
    const int kvh = h / GQ_;
    const int t0q = itq * 128;
    const int jmax = 2 * itq + 1;

    #pragma unroll
    for (int p = 0; p < 8; ++p) {
        int idx = tid + p * 256;
        int r = (idx >> 4) & 127, c = idx & 15;
        cp16(sb + r * FST + c * 16,
             qH + ((size_t)(b * T_ + t0q + r) * NH_ + h) * HD_ + c * 8);
    }
    #pragma unroll
    for (int p = 0; p < 8; ++p) {
        int idx = tid + p * 256;
        int part = idx >> 10;
        int r = (idx >> 4) & 63, c = idx & 15;
        const __half* src = part ? vH : kH;
        cp16(sb + QT + part * KVP + r * FST + c * 16,
             src + ((size_t)(b * T_ + r) * NKV_ + kvh) * HD_ + c * 8);
    }
    CP_COMMIT();
    CP_WAIT0();
    __syncthreads();

    uint32_t QF[8][4];
    #pragma unroll
    for (int ks = 0; ks < 8; ++ks) {
        uint32_t ra = sb + (wid * 16 + (lane & 15)) * FST
                    + ks * 32 + ((lane >> 4) << 4);
        ldsm_x4(QF[ks], ra);
    }

    float m0 = NEG_INF, m1 = NEG_INF, l0 = 0.f, l1 = 0.f;
    float O[16][4];
    #pragma unroll
    for (int nt = 0; nt < 16; ++nt)
        #pragma unroll
        for (int j = 0; j < 4; ++j) O[nt][j] = 0.f;

    const int row_a = t0q + wid * 16 + (lane >> 2);

    for (int jt = 0; jt <= jmax; ++jt) {
        const int buf = jt & 1;
        if (jt > 0) { CP_WAIT0(); __syncthreads(); }
        if (jt + 1 <= jmax) {
            const int t0n = (jt + 1) * 64;
            #pragma unroll
            for (int p = 0; p < 8; ++p) {
                int idx = tid + p * 256;
                int part = idx >> 10;
                int r = (idx >> 4) & 63, c = idx & 15;
                const __half* src = part ? vH : kH;
                cp16(sb + QT + (buf ^ 1) * STG + part * KVP + r * FST + c * 16,
                     src + ((size_t)(b * T_ + t0n + r) * NKV_ + kvh) * HD_ + c * 8);
            }
            CP_COMMIT();
        }

        const uint32_t base_k = sb + QT + buf * STG;
        const int t0k = jt * 64;

        float S[8][4];
        #pragma unroll
        for (int nt = 0; nt < 8; ++nt)
            #pragma unroll
            for (int j = 0; j < 4; ++j) S[nt][j] = 0.f;

        #pragma unroll
        for (int ks = 0; ks < 8; ++ks) {
            #pragma unroll
            for (int ntp = 0; ntp < 4; ++ntp) {
                uint32_t bh[4];
                uint32_t rb = base_k
                            + (ntp * 16 + (lane & 7) + ((lane >> 4) << 3)) * FST
                            + ks * 32 + (((lane >> 3) & 1) << 4);
                ldsm_x4(bh, rb);
                mma_f16(S[2 * ntp],     QF[ks], bh);
                mma_f16(S[2 * ntp + 1], QF[ks], bh + 2);
            }
        }

        const bool diag = (jt >= 2 * itq);
        float ml0 = NEG_INF, ml1 = NEG_INF;
        #pragma unroll
        for (int nt = 0; nt < 8; ++nt) {
            int c = t0k + nt * 8 + 2 * (lane & 3);
            if (diag) {
                if (c     > row_a)     S[nt][0] = NEG_INF;
                if (c + 1 > row_a)     S[nt][1] = NEG_INF;
                if (c     > row_a + 8) S[nt][2] = NEG_INF;
                if (c + 1 > row_a + 8) S[nt][3] = NEG_INF;
            }
            ml0 = fmaxf(ml0, fmaxf(S[nt][0], S[nt][1]));
            ml1 = fmaxf(ml1, fmaxf(S[nt][2], S[nt][3]));
        }
        ml0 = fmaxf(ml0, __shfl_xor_sync(0xffffffffu, ml0, 1));
        ml0 = fmaxf(ml0, __shfl_xor_sync(0xffffffffu, ml0, 2));
        ml1 = fmaxf(ml1, __shfl_xor_sync(0xffffffffu, ml1, 1));
        ml1 = fmaxf(ml1, __shfl_xor_sync(0xffffffffu, ml1, 2));

        float mn0 = fmaxf(m0, ml0), mn1 = fmaxf(m1, ml1);
        float es0 = exp2f(m0 - mn0);
        float es1 = exp2f(m1 - mn1);
        m0 = mn0; m1 = mn1;

        float sum0 = 0.f, sum1 = 0.f;
        uint32_t PH[16];
        #pragma unroll
        for (int nt = 0; nt < 8; ++nt) {
            float p0 = exp2f(S[nt][0] - mn0);
            float p1 = exp2f(S[nt][1] - mn0);
            float p2 = exp2f(S[nt][2] - mn1);
            float p3 = exp2f(S[nt][3] - mn1);
            sum0 += p0 + p1;  sum1 += p2 + p3;
            __half2 hA = __floats2half2_rn(p0, p1);
            __half2 hB = __floats2half2_rn(p2, p3);
            PH[2 * nt]     = *(uint32_t*)&hA;
            PH[2 * nt + 1] = *(uint32_t*)&hB;
        }
        sum0 += __shfl_xor_sync(0xffffffffu, sum0, 1);
        sum0 += __shfl_xor_sync(0xffffffffu, sum0, 2);
        sum1 += __shfl_xor_sync(0xffffffffu, sum1, 1);
        sum1 += __shfl_xor_sync(0xffffffffu, sum1, 2);
        l0 = l0 * es0 + sum0;
        l1 = l1 * es1 + sum1;
        #pragma unroll
        for (int nt = 0; nt < 16; ++nt) {
            O[nt][0] *= es0; O[nt][1] *= es0;
            O[nt][2] *= es1; O[nt][3] *= es1;
        }

        const uint32_t base_v = base_k + KVP;
        #pragma unroll
        for (int kt = 0; kt < 4; ++kt) {
            uint32_t pa[4] = { PH[4*kt], PH[4*kt+1], PH[4*kt+2], PH[4*kt+3] };
            #pragma unroll
            for (int ntp = 0; ntp < 8; ++ntp) {
                uint32_t bh[4];
                uint32_t rv = base_v
                            + (kt * 16 + (lane & 7) + (lane & 8)) * FST
                            + ntp * 32 + ((lane >> 4) << 4);
                ldsm_x4_t(bh, rv);
                mma_f16(O[2 * ntp],     pa, bh);
                mma_f16(O[2 * ntp + 1], pa, bh + 2);
            }
        }
    }

    // ---- epilogue: normalize -> fp16 y ----
    float inv0 = 1.f / l0, inv1 = 1.f / l1;
    #pragma unroll
    for (int nt = 0; nt < 16; ++nt) {
        int c = nt * 8 + 2 * (lane & 3);
        size_t baseA = ((size_t)(b * T_ + row_a) * NH_ + h) * HD_ + c;
        size_t baseB = ((size_t)(b * T_ + row_a + 8) * NH_ + h) * HD_ + c;
        __half2 uA = __floats2half2_rn(O[nt][0] * inv0, O[nt][1] * inv0);
        __half2 uB = __floats2half2_rn(O[nt][2] * inv1, O[nt][3] * inv1);
        *(uint32_t*)(y + baseA) = *(uint32_t*)&uA;
        *(uint32_t*)(y + baseB) = *(uint32_t*)&uB;
    }
}

// ---------------------------------------------------------------------------
extern "C" void kernel_launch(void* const* d_in, const int* in_sizes, int n_in,
                              void* d_out, int out_size)
{
    const float* x  = (const float*)d_in[0];
    const float* Wq = (const float*)d_in[1];
    const float* Wk = (const float*)d_in[2];
    const float* Wv = (const float*)d_in[3];
    const float* Wp = (const float*)d_in[4];
    const float* qg = (const float*)d_in[5];
    float* out = (float*)d_out;

    float *q, *kk;
    cudaGetSymbolAddress((void**)&q,  g_q);
    cudaGetSymbolAddress((void**)&kk, g_k);
    __half *xH, *wvH, *wpH, *qh16, *kh16, *vh16, *yH;
    cudaGetSymbolAddress((void**)&xH,  g_xH);
    cudaGetSymbolAddress((void**)&wvH, g_wvH);
    cudaGetSymbolAddress((void**)&wpH, g_wpH);
    cudaGetSymbolAddress((void**)&qh16, g_qH);
    cudaGetSymbolAddress((void**)&kh16, g_kH);
    cudaGetSymbolAddress((void**)&vh16, g_vH);
    cudaGetSymbolAddress((void**)&yH,  g_yH);
    __nv_bfloat16 *xh,*xl,*wqh,*wql,*wkh,*wkl;
    cudaGetSymbolAddress((void**)&xh,  g_xh);  cudaGetSymbolAddress((void**)&xl,  g_xl);
    cudaGetSymbolAddress((void**)&wqh, g_wqh); cudaGetSymbolAddress((void**)&wql, g_wql);
    cudaGetSymbolAddress((void**)&wkh, g_wkh); cudaGetSymbolAddress((void**)&wkl, g_wkl);

    cudaFuncSetAttribute(gemm_hl,  cudaFuncAttributeMaxDynamicSharedMemorySize, GSMEM);
    cudaFuncSetAttribute(gemm_f16, cudaFuncAttributeMaxDynamicSharedMemorySize, HSMEM);
    cudaFuncSetAttribute(flash_mma, cudaFuncAttributeMaxDynamicSharedMemorySize, FSMEM);

    // (0) RoPE tables, (1) operand prep
    rope_table_kernel<<<(T_ * 64 + 255) / 256, 256>>>();
    split_all_kernel<<<SPLIT_TOT / 256, 256>>>(x, Wq, Wk, Wv, Wp);

    dim3 gq(DIM_ / 128, (B_ * T_) / 128);   // (16,32)
    dim3 gk(KD_  / 128, (B_ * T_) / 128);   // (4,32)

    // (2) K proj (3-term), (3) Q proj (3-term) [profiled slot]
    gemm_hl<<<gk, 512, GSMEM>>>(xh, xl, wkh, wkl, kk, KD_,  DIM_);
    gemm_hl<<<gq, 512, GSMEM>>>(xh, xl, wqh, wql, q,  DIM_, DIM_);

    // (4) V proj (fp16 1-term) -> vH
    gemm_f16<<<gk, 256, HSMEM>>>(xH, wvH, nullptr, vh16, KD_, DIM_);

    // (5,6) RMSNorm + RoPE -> fp16
    const float QMUL = 0.08838834764831845f * 1.44269504088896340736f;
    norm_rope_kernel<<<(B_ * T_ * NH_  * 32) / 256, 256>>>(q,  qg,      NH_,  QMUL, qh16);
    norm_rope_kernel<<<(B_ * T_ * NKV_ * 32) / 256, 256>>>(kk, nullptr, NKV_, 1.0f, kh16);

    // (7) flash attention -> y fp16
    flash_mma<<<dim3(T_ / 128, NH_, B_), 256, FSMEM>>>(qh16, kh16, vh16, yH);

    // (8) out proj (fp16 1-term) -> fp32 out
    gemm_f16<<<gq, 256, HSMEM>>>(yH, wpH, out, nullptr, DIM_, DIM_);
}